// round 8
// baseline (speedup 1.0000x reference)
#include <cuda_runtime.h>
#include <math.h>

// Problem dims (fixed by setup_inputs)
#define ND 50000
#define FD 128
#define NC 10000
#define FC 735
#define FCP 736        // padded K for cell MLP1
#define ED 800000
#define EC 160000
#define BATCH 16384

// ------------------------- scratch (device globals) -------------------------
__device__ float g_d0[ND * 256];
__device__ float g_dx[ND * 256];
__device__ float g_dagg[ND * 256];
__device__ float g_c0[NC * 1024];
__device__ float g_c1[NC * 256];
__device__ float g_cx1[NC * 1024];
__device__ float g_cagg1[NC * 1024];
__device__ float g_cx2[NC * 256];
__device__ float g_cagg2[NC * 256];
__device__ float g_as[ND];
__device__ float g_ad[ND];
__device__ float g_alpha[ED + ND];
__device__ int   g_off[ND + 1];
__device__ int   g_cnt[ND];
__device__ int   g_bsum[64];
__device__ int   g_csrc[ED + ND];
__device__ float g_cxp[NC * FCP];      // padded cell_x
__device__ float g_w1p[FCP * 1024];    // padded cW1
__device__ float g_comb[BATCH * 512];
__device__ float g_h1[BATCH * 512];
__device__ float g_h2[BATCH * 512];

// ------------------------- SGEMM -------------------------
// C[M,N] = act(A[M,K] @ B[K,N] + bias). Row-major. BN=128, BK=8, 256 threads.
// Requires: K % 8 == 0, N % 128 == 0.  act: 0 none, 1 relu, 2 elu.
template<int BM, int TM>
__global__ __launch_bounds__(256, 2)
void sgemm2_kernel(const float* __restrict__ A, const float* __restrict__ B,
                   const float* __restrict__ bias, float* __restrict__ C,
                   int M, int N, int K, int act) {
    __shared__ float As[2][8][BM];
    __shared__ float Bs[2][8][128];
    const int tid = threadIdx.x;
    const int tx = tid & 15;        // col group (0..15), 8 cols each
    const int ty = tid >> 4;        // row group (0..15), TM rows each
    const int mbase = blockIdx.y * BM;
    const int nbase = blockIdx.x * 128;

    const int arow = tid >> 1;          // A: 2 threads per row (8 k / 4)
    const int ak   = (tid & 1) * 4;
    const int brow = tid >> 5;          // B: 32 threads per k-row
    const int bcol = (tid & 31) * 4;
    const bool aval = (BM == 128) || (tid < 128);

    float4 ra = make_float4(0.f, 0.f, 0.f, 0.f), rb;
    // prologue: tile 0
    {
        int gm = mbase + arow;
        if (aval && gm < M) ra = *(const float4*)&A[(size_t)gm * K + ak];
        rb = *(const float4*)&B[(size_t)brow * N + nbase + bcol];
    }
    if (aval) {
        As[0][ak + 0][arow] = ra.x; As[0][ak + 1][arow] = ra.y;
        As[0][ak + 2][arow] = ra.z; As[0][ak + 3][arow] = ra.w;
    }
    *(float4*)&Bs[0][brow][bcol] = rb;
    __syncthreads();

    float acc[TM][8];
#pragma unroll
    for (int i = 0; i < TM; i++)
#pragma unroll
        for (int j = 0; j < 8; j++) acc[i][j] = 0.f;

    const int nk = K >> 3;
    for (int t = 1; t <= nk; t++) {
        const int cur = (t - 1) & 1, nxt = t & 1;
        if (t < nk) {
            int k0 = t * 8;
            int gm = mbase + arow;
            ra = make_float4(0.f, 0.f, 0.f, 0.f);
            if (aval && gm < M) ra = *(const float4*)&A[(size_t)gm * K + k0 + ak];
            rb = *(const float4*)&B[(size_t)(k0 + brow) * N + nbase + bcol];
        }
#pragma unroll
        for (int k = 0; k < 8; k++) {
            float a[TM], b[8];
            float4 a0 = *(const float4*)&As[cur][k][ty * TM];
            a[0] = a0.x; a[1] = a0.y; a[2] = a0.z; a[3] = a0.w;
            if (TM == 8) {
                float4 a1 = *(const float4*)&As[cur][k][ty * TM + 4];
                a[4] = a1.x; a[5] = a1.y; a[6] = a1.z; a[7] = a1.w;
            }
            float4 b0 = *(const float4*)&Bs[cur][k][tx * 8];
            float4 b1 = *(const float4*)&Bs[cur][k][tx * 8 + 4];
            b[0] = b0.x; b[1] = b0.y; b[2] = b0.z; b[3] = b0.w;
            b[4] = b1.x; b[5] = b1.y; b[6] = b1.z; b[7] = b1.w;
#pragma unroll
            for (int i = 0; i < TM; i++)
#pragma unroll
                for (int j = 0; j < 8; j++)
                    acc[i][j] = fmaf(a[i], b[j], acc[i][j]);
        }
        if (t < nk) {
            if (aval) {
                As[nxt][ak + 0][arow] = ra.x; As[nxt][ak + 1][arow] = ra.y;
                As[nxt][ak + 2][arow] = ra.z; As[nxt][ak + 3][arow] = ra.w;
            }
            *(float4*)&Bs[nxt][brow][bcol] = rb;
        }
        __syncthreads();
    }

    // epilogue
    float bv[8];
    if (bias) {
        float4 q0 = *(const float4*)&bias[nbase + tx * 8];
        float4 q1 = *(const float4*)&bias[nbase + tx * 8 + 4];
        bv[0] = q0.x; bv[1] = q0.y; bv[2] = q0.z; bv[3] = q0.w;
        bv[4] = q1.x; bv[5] = q1.y; bv[6] = q1.z; bv[7] = q1.w;
    } else {
#pragma unroll
        for (int j = 0; j < 8; j++) bv[j] = 0.f;
    }
#pragma unroll
    for (int i = 0; i < TM; i++) {
        int gm = mbase + ty * TM + i;
        if (gm >= M) break;
        float o[8];
#pragma unroll
        for (int j = 0; j < 8; j++) {
            float v = acc[i][j] + bv[j];
            if (act == 1) v = v > 0.f ? v : 0.f;
            else if (act == 2) v = v > 0.f ? v : (expf(v) - 1.f);
            o[j] = v;
        }
        float* crow = C + (size_t)gm * N + nbase + tx * 8;
        *(float4*)&crow[0] = make_float4(o[0], o[1], o[2], o[3]);
        *(float4*)&crow[4] = make_float4(o[4], o[5], o[6], o[7]);
    }
}

static inline void sgemm128(const float* A, const float* B, const float* bias,
                            float* C, int M, int N, int K, int act) {
    dim3 g(N / 128, (M + 127) / 128);
    sgemm2_kernel<128, 8><<<g, 256>>>(A, B, bias, C, M, N, K, act);
}
static inline void sgemm64(const float* A, const float* B, const float* bias,
                           float* C, int M, int N, int K, int act) {
    dim3 g(N / 128, (M + 63) / 64);
    sgemm2_kernel<64, 4><<<g, 256>>>(A, B, bias, C, M, N, K, act);
}

// ------------------------- padding kernels -------------------------
__global__ void pad_cellx_kernel(const float* __restrict__ src, float* __restrict__ dst) {
    int i = blockIdx.x * blockDim.x + threadIdx.x;
    if (i >= NC * FCP) return;
    int r = i / FCP, k = i - r * FCP;
    dst[i] = (k < FC) ? src[(size_t)r * FC + k] : 0.f;
}
__global__ void pad_w1_kernel(const float* __restrict__ src, float* __restrict__ dst) {
    int i = blockIdx.x * blockDim.x + threadIdx.x;
    if (i >= FCP * 1024) return;
    int k = i >> 10;
    dst[i] = (k < FC) ? src[i] : 0.f;   // same layout for k < FC
}

// ------------------------- CSR build -------------------------
__global__ void hist_kernel(const int* __restrict__ ei, int E, int n, int* __restrict__ cnt) {
    int i = blockIdx.x * blockDim.x + threadIdx.x;
    if (i >= E + n) return;
    int d = (i < E) ? ei[E + i] : (i - E);
    atomicAdd(&cnt[d], 1);
}

__global__ void scan_block_kernel(const int* __restrict__ cnt, int* __restrict__ off,
                                  int* __restrict__ bsum, int n) {
    __shared__ int sh[1024];
    int t = threadIdx.x;
    int i = blockIdx.x * 1024 + t;
    int v = (i < n) ? cnt[i] : 0;
    sh[t] = v;
    __syncthreads();
    for (int o = 1; o < 1024; o <<= 1) {
        int x = (t >= o) ? sh[t - o] : 0;
        __syncthreads();
        sh[t] += x;
        __syncthreads();
    }
    if (i < n) off[i] = sh[t] - v;          // exclusive
    if (t == 1023) bsum[blockIdx.x] = sh[t];
}

__global__ void scan_add_kernel(int* __restrict__ off, const int* __restrict__ bsum,
                                int nblocks, int n, int total) {
    __shared__ int pre[64];
    if (threadIdx.x == 0) {
        int s = 0;
        for (int b = 0; b < nblocks; b++) { pre[b] = s; s += bsum[b]; }
    }
    __syncthreads();
    int i = blockIdx.x * blockDim.x + threadIdx.x;
    if (i < n) off[i] += pre[i >> 10];
    if (i == 0) off[n] = total;
}

__global__ void scatter_kernel(const int* __restrict__ ei, int E, int n,
                               const int* __restrict__ off, int* __restrict__ fill,
                               int* __restrict__ csrc) {
    int i = blockIdx.x * blockDim.x + threadIdx.x;
    if (i >= E + n) return;
    int s, d;
    if (i < E) { s = ei[i]; d = ei[E + i]; } else { s = d = i - E; }
    int pos = off[d] + atomicAdd(&fill[d], 1);
    csrc[pos] = s;
}

// ------------------------- GAT pieces -------------------------
__global__ void node_dots_kernel(const float* __restrict__ x,
                                 const float* __restrict__ asrc,
                                 const float* __restrict__ adst,
                                 float* __restrict__ out_s, float* __restrict__ out_d,
                                 int n, int F) {
    int w = (int)((blockIdx.x * (size_t)blockDim.x + threadIdx.x) >> 5);
    int lane = threadIdx.x & 31;
    if (w >= n) return;
    const float* xr = x + (size_t)w * F;
    float s = 0.f, d = 0.f;
    for (int f = lane; f < F; f += 32) {
        float v = xr[f];
        s = fmaf(v, asrc[f], s);
        d = fmaf(v, adst[f], d);
    }
#pragma unroll
    for (int o = 16; o; o >>= 1) {
        s += __shfl_xor_sync(0xffffffffu, s, o);
        d += __shfl_xor_sync(0xffffffffu, d, o);
    }
    if (lane == 0) { out_s[w] = s; out_d[w] = d; }
}

// warp-per-node segment softmax over CSR edges; writes normalized alpha
__global__ void csr_softmax_kernel(const int* __restrict__ off, const int* __restrict__ csrc,
                                   const float* __restrict__ as_, const float* __restrict__ ad_,
                                   float* __restrict__ alpha, int n) {
    int w = (int)((blockIdx.x * (size_t)blockDim.x + threadIdx.x) >> 5);
    int lane = threadIdx.x & 31;
    if (w >= n) return;
    int beg = off[w], end = off[w + 1];
    float add = ad_[w];
    float m = -1e30f;
    for (int j = beg + lane; j < end; j += 32) {
        float e = as_[csrc[j]] + add;
        e = e > 0.f ? e : 0.2f * e;
        m = fmaxf(m, e);
    }
#pragma unroll
    for (int o = 16; o; o >>= 1) m = fmaxf(m, __shfl_xor_sync(0xffffffffu, m, o));
    float s = 0.f;
    for (int j = beg + lane; j < end; j += 32) {
        float e = as_[csrc[j]] + add;
        e = e > 0.f ? e : 0.2f * e;
        float v = expf(e - m);
        alpha[j] = v;
        s += v;
    }
#pragma unroll
    for (int o = 16; o; o >>= 1) s += __shfl_xor_sync(0xffffffffu, s, o);
    float inv = 1.f / s;
    for (int j = beg + lane; j < end; j += 32) alpha[j] *= inv;
}

// block-per-node gather: out[d,:] = relu(sum_e alpha[e]*x[src[e],:] + bias)
template<int F>
__global__ void csr_gather_kernel(const int* __restrict__ off, const int* __restrict__ csrc,
                                  const float* __restrict__ alpha,
                                  const float* __restrict__ x,
                                  const float* __restrict__ bias,
                                  float* __restrict__ out) {
    constexpr int FPT = F / 256;
    int d = blockIdx.x;
    int t = threadIdx.x;
    int beg = off[d], end = off[d + 1];
    float acc[FPT];
#pragma unroll
    for (int q = 0; q < FPT; q++) acc[q] = 0.f;

    int j = beg;
    for (; j + 1 < end; j += 2) {
        int s0 = csrc[j], s1 = csrc[j + 1];
        float a0 = alpha[j], a1 = alpha[j + 1];
        const float* x0 = x + (size_t)s0 * F;
        const float* x1 = x + (size_t)s1 * F;
#pragma unroll
        for (int q = 0; q < FPT; q++)
            acc[q] = fmaf(a1, x1[t + q * 256], fmaf(a0, x0[t + q * 256], acc[q]));
    }
    if (j < end) {
        int s0 = csrc[j];
        float a0 = alpha[j];
        const float* x0 = x + (size_t)s0 * F;
#pragma unroll
        for (int q = 0; q < FPT; q++)
            acc[q] = fmaf(a0, x0[t + q * 256], acc[q]);
    }
    float* orow = out + (size_t)d * F;
#pragma unroll
    for (int q = 0; q < FPT; q++) {
        float v = acc[q] + bias[t + q * 256];
        orow[t + q * 256] = v > 0.f ? v : 0.f;
    }
}

// ------------------------- misc -------------------------
__global__ void gather_comb_kernel(const float* __restrict__ dsrc, const float* __restrict__ csrc,
                                   const int* __restrict__ di, const int* __restrict__ ci,
                                   float* __restrict__ comb) {
    int b = blockIdx.x;
    int t = threadIdx.x;
    comb[(size_t)b * 512 + t] = dsrc[(size_t)di[b] * 256 + t];
    comb[(size_t)b * 512 + 256 + t] = csrc[(size_t)ci[b] * 256 + t];
}

__global__ void head_final_kernel(const float* __restrict__ h, const float* __restrict__ W,
                                  const float* __restrict__ b, float* __restrict__ out) {
    size_t gt = blockIdx.x * (size_t)blockDim.x + threadIdx.x;
    int r = (int)(gt >> 5);
    int lane = threadIdx.x & 31;
    if (r >= BATCH) return;
    const float* hr = h + (size_t)r * 512;
    float s = 0.f;
    for (int f = lane; f < 512; f += 32) s = fmaf(hr[f], W[f], s);
#pragma unroll
    for (int o = 16; o; o >>= 1) s += __shfl_xor_sync(0xffffffffu, s, o);
    if (lane == 0) out[r] = s + b[0];
}

// ------------------------- host side -------------------------
static void build_csr(const int* ei, int E, int n, int* cnt, int* off, int* bsum, int* csrc) {
    cudaMemsetAsync(cnt, 0, n * sizeof(int));
    int total = E + n;
    hist_kernel<<<(total + 255) / 256, 256>>>(ei, E, n, cnt);
    int nblocks = (n + 1023) / 1024;
    scan_block_kernel<<<nblocks, 1024>>>(cnt, off, bsum, n);
    scan_add_kernel<<<(n + 255) / 256, 256>>>(off, bsum, nblocks, n, total);
    cudaMemsetAsync(cnt, 0, n * sizeof(int));
    scatter_kernel<<<(total + 255) / 256, 256>>>(ei, E, n, off, cnt, csrc);
}

static void run_gat_csr(const int* off, const int* csrc, int n, int F,
                        const float* x, const float* avec_s, const float* avec_d,
                        const float* bias, float* as_, float* ad_, float* alpha, float* out) {
    size_t threads = (size_t)n * 32;
    node_dots_kernel<<<(unsigned)((threads + 255) / 256), 256>>>(x, avec_s, avec_d, as_, ad_, n, F);
    csr_softmax_kernel<<<(unsigned)((threads + 255) / 256), 256>>>(off, csrc, as_, ad_, alpha, n);
    if (F == 1024)
        csr_gather_kernel<1024><<<n, 256>>>(off, csrc, alpha, x, bias, out);
    else
        csr_gather_kernel<256><<<n, 256>>>(off, csrc, alpha, x, bias, out);
}

extern "C" void kernel_launch(void* const* d_in, const int* in_sizes, int n_in,
                              void* d_out, int out_size) {
    const float* drug_x = (const float*)d_in[0];
    const float* cell_x = (const float*)d_in[1];
    const int* dei = (const int*)d_in[2];
    const int* cei = (const int*)d_in[3];
    const int* didx = (const int*)d_in[4];
    const int* cidx = (const int*)d_in[5];
    const float* dW1 = (const float*)d_in[6];  const float* db1 = (const float*)d_in[7];
    const float* cW1 = (const float*)d_in[8];  const float* cb1 = (const float*)d_in[9];
    const float* cW2 = (const float*)d_in[10]; const float* cb2 = (const float*)d_in[11];
    const float* gdW = (const float*)d_in[12]; const float* gdas = (const float*)d_in[13];
    const float* gdad = (const float*)d_in[14]; const float* gdb = (const float*)d_in[15];
    const float* g1W = (const float*)d_in[16]; const float* g1as = (const float*)d_in[17];
    const float* g1ad = (const float*)d_in[18]; const float* g1b = (const float*)d_in[19];
    const float* g2W = (const float*)d_in[20]; const float* g2as = (const float*)d_in[21];
    const float* g2ad = (const float*)d_in[22]; const float* g2b = (const float*)d_in[23];
    const float* rW1 = (const float*)d_in[24]; const float* rb1 = (const float*)d_in[25];
    const float* rW2 = (const float*)d_in[26]; const float* rb2 = (const float*)d_in[27];
    const float* rW3 = (const float*)d_in[28]; const float* rb3 = (const float*)d_in[29];
    float* out = (float*)d_out;

    float *p_d0, *p_dx, *p_dagg, *p_c0, *p_c1, *p_cx1, *p_cagg1, *p_cx2, *p_cagg2;
    float *p_as, *p_ad, *p_alpha, *p_cxp, *p_w1p, *p_comb, *p_h1, *p_h2;
    int *p_off, *p_cnt, *p_bsum, *p_csrc;
    cudaGetSymbolAddress((void**)&p_d0, g_d0);
    cudaGetSymbolAddress((void**)&p_dx, g_dx);
    cudaGetSymbolAddress((void**)&p_dagg, g_dagg);
    cudaGetSymbolAddress((void**)&p_c0, g_c0);
    cudaGetSymbolAddress((void**)&p_c1, g_c1);
    cudaGetSymbolAddress((void**)&p_cx1, g_cx1);
    cudaGetSymbolAddress((void**)&p_cagg1, g_cagg1);
    cudaGetSymbolAddress((void**)&p_cx2, g_cx2);
    cudaGetSymbolAddress((void**)&p_cagg2, g_cagg2);
    cudaGetSymbolAddress((void**)&p_as, g_as);
    cudaGetSymbolAddress((void**)&p_ad, g_ad);
    cudaGetSymbolAddress((void**)&p_alpha, g_alpha);
    cudaGetSymbolAddress((void**)&p_off, g_off);
    cudaGetSymbolAddress((void**)&p_cnt, g_cnt);
    cudaGetSymbolAddress((void**)&p_bsum, g_bsum);
    cudaGetSymbolAddress((void**)&p_csrc, g_csrc);
    cudaGetSymbolAddress((void**)&p_cxp, g_cxp);
    cudaGetSymbolAddress((void**)&p_w1p, g_w1p);
    cudaGetSymbolAddress((void**)&p_comb, g_comb);
    cudaGetSymbolAddress((void**)&p_h1, g_h1);
    cudaGetSymbolAddress((void**)&p_h2, g_h2);

    // ---- padding for K=735 GEMM ----
    pad_cellx_kernel<<<(NC * FCP + 255) / 256, 256>>>(cell_x, p_cxp);
    pad_w1_kernel<<<(FCP * 1024 + 255) / 256, 256>>>(cW1, p_w1p);

    // ---- feature transforms ----
    sgemm128(drug_x, dW1, db1, p_d0, ND, 256, FD, 1);
    sgemm128(p_cxp, p_w1p, cb1, p_c0, NC, 1024, FCP, 1);
    sgemm64(p_c0, cW2, cb2, p_c1, NC, 256, 1024, 1);

    // ---- drug GAT (256 -> 256) ----
    sgemm128(p_d0, gdW, nullptr, p_dx, ND, 256, 256, 0);
    build_csr(dei, ED, ND, p_cnt, p_off, p_bsum, p_csrc);
    run_gat_csr(p_off, p_csrc, ND, 256, p_dx, gdas, gdad, gdb, p_as, p_ad, p_alpha, p_dagg);

    // ---- cell GAT1 (256 -> 1024) ----
    sgemm128(p_c1, g1W, nullptr, p_cx1, NC, 1024, 256, 0);
    build_csr(cei, EC, NC, p_cnt, p_off, p_bsum, p_csrc);   // shared by GAT1 + GAT2
    run_gat_csr(p_off, p_csrc, NC, 1024, p_cx1, g1as, g1ad, g1b, p_as, p_ad, p_alpha, p_cagg1);

    // ---- cell GAT2 (1024 -> 256) ----
    sgemm64(p_cagg1, g2W, nullptr, p_cx2, NC, 256, 1024, 0);
    run_gat_csr(p_off, p_csrc, NC, 256, p_cx2, g2as, g2ad, g2b, p_as, p_ad, p_alpha, p_cagg2);

    // ---- pair gather + regression head ----
    gather_comb_kernel<<<BATCH, 256>>>(p_dagg, p_cagg2, didx, cidx, p_comb);
    sgemm128(p_comb, rW1, rb1, p_h1, BATCH, 512, 512, 2);
    sgemm128(p_h1, rW2, rb2, p_h2, BATCH, 512, 512, 2);
    head_final_kernel<<<(BATCH * 32 + 255) / 256, 256>>>(p_h2, rW3, rb3, out);
}

// round 9
// speedup vs baseline: 1.0462x; 1.0462x over previous
#include <cuda_runtime.h>
#include <math.h>

// Problem dims (fixed by setup_inputs)
#define ND 50000
#define FD 128
#define NC 10000
#define FC 735
#define FCP 736        // padded K for cell MLP1
#define ED 800000
#define EC 160000
#define BATCH 16384

// ------------------------- scratch (device globals) -------------------------
__device__ float g_d0[ND * 256];
__device__ float g_dx[ND * 256];
__device__ float g_dagg[ND * 256];
__device__ float g_c0[NC * 1024];
__device__ float g_c1[NC * 256];
__device__ float g_cx1[NC * 1024];
__device__ float g_cagg1[NC * 1024];
__device__ float g_cx2[NC * 256];
__device__ float g_cagg2[NC * 256];
__device__ float g_as[ND];
__device__ float g_ad[ND];
__device__ float g_alpha[ED + ND];
__device__ int   g_off[ND + 1];
__device__ int   g_cnt[ND];
__device__ int   g_bsum[64];
__device__ int   g_csrc[ED + ND];
__device__ float g_cxp[NC * FCP];      // padded cell_x
__device__ float g_w1p[FCP * 1024];    // padded cW1
__device__ float g_comb[BATCH * 512];
__device__ float g_h1[BATCH * 512];
__device__ float g_h2[BATCH * 512];

// ------------------------- SGEMM -------------------------
// C[M,N] = act(A[M,K] @ B[K,N] + bias). Row-major. BN=128, BK=8, 256 threads.
// Requires: K % 8 == 0, N % 128 == 0.  act: 0 none, 1 relu, 2 elu.
template<int BM, int TM>
__global__ __launch_bounds__(256, 2)
void sgemm2_kernel(const float* __restrict__ A, const float* __restrict__ B,
                   const float* __restrict__ bias, float* __restrict__ C,
                   int M, int N, int K, int act) {
    __shared__ float As[2][8][BM];
    __shared__ float Bs[2][8][128];
    const int tid = threadIdx.x;
    const int tx = tid & 15;        // col group (0..15), 8 cols each
    const int ty = tid >> 4;        // row group (0..15), TM rows each
    const int mbase = blockIdx.y * BM;
    const int nbase = blockIdx.x * 128;

    const int arow = tid >> 1;          // A: 2 threads per row (8 k / 4)
    const int ak   = (tid & 1) * 4;
    const int brow = tid >> 5;          // B: 32 threads per k-row
    const int bcol = (tid & 31) * 4;
    const bool aval = (BM == 128) || (tid < 128);

    float4 ra = make_float4(0.f, 0.f, 0.f, 0.f), rb;
    // prologue: tile 0
    {
        int gm = mbase + arow;
        if (aval && gm < M) ra = *(const float4*)&A[(size_t)gm * K + ak];
        rb = *(const float4*)&B[(size_t)brow * N + nbase + bcol];
    }
    if (aval) {
        As[0][ak + 0][arow] = ra.x; As[0][ak + 1][arow] = ra.y;
        As[0][ak + 2][arow] = ra.z; As[0][ak + 3][arow] = ra.w;
    }
    *(float4*)&Bs[0][brow][bcol] = rb;
    __syncthreads();

    float acc[TM][8];
#pragma unroll
    for (int i = 0; i < TM; i++)
#pragma unroll
        for (int j = 0; j < 8; j++) acc[i][j] = 0.f;

    const int nk = K >> 3;
    for (int t = 1; t <= nk; t++) {
        const int cur = (t - 1) & 1, nxt = t & 1;
        if (t < nk) {
            int k0 = t * 8;
            int gm = mbase + arow;
            ra = make_float4(0.f, 0.f, 0.f, 0.f);
            if (aval && gm < M) ra = *(const float4*)&A[(size_t)gm * K + k0 + ak];
            rb = *(const float4*)&B[(size_t)(k0 + brow) * N + nbase + bcol];
        }
#pragma unroll
        for (int k = 0; k < 8; k++) {
            float a[TM], b[8];
            float4 a0 = *(const float4*)&As[cur][k][ty * TM];
            a[0] = a0.x; a[1] = a0.y; a[2] = a0.z; a[3] = a0.w;
            if (TM == 8) {
                float4 a1 = *(const float4*)&As[cur][k][ty * TM + 4];
                a[4] = a1.x; a[5] = a1.y; a[6] = a1.z; a[7] = a1.w;
            }
            float4 b0 = *(const float4*)&Bs[cur][k][tx * 8];
            float4 b1 = *(const float4*)&Bs[cur][k][tx * 8 + 4];
            b[0] = b0.x; b[1] = b0.y; b[2] = b0.z; b[3] = b0.w;
            b[4] = b1.x; b[5] = b1.y; b[6] = b1.z; b[7] = b1.w;
#pragma unroll
            for (int i = 0; i < TM; i++)
#pragma unroll
                for (int j = 0; j < 8; j++)
                    acc[i][j] = fmaf(a[i], b[j], acc[i][j]);
        }
        if (t < nk) {
            if (aval) {
                As[nxt][ak + 0][arow] = ra.x; As[nxt][ak + 1][arow] = ra.y;
                As[nxt][ak + 2][arow] = ra.z; As[nxt][ak + 3][arow] = ra.w;
            }
            *(float4*)&Bs[nxt][brow][bcol] = rb;
        }
        __syncthreads();
    }

    // epilogue
    float bv[8];
    if (bias) {
        float4 q0 = *(const float4*)&bias[nbase + tx * 8];
        float4 q1 = *(const float4*)&bias[nbase + tx * 8 + 4];
        bv[0] = q0.x; bv[1] = q0.y; bv[2] = q0.z; bv[3] = q0.w;
        bv[4] = q1.x; bv[5] = q1.y; bv[6] = q1.z; bv[7] = q1.w;
    } else {
#pragma unroll
        for (int j = 0; j < 8; j++) bv[j] = 0.f;
    }
#pragma unroll
    for (int i = 0; i < TM; i++) {
        int gm = mbase + ty * TM + i;
        if (gm >= M) break;
        float o[8];
#pragma unroll
        for (int j = 0; j < 8; j++) {
            float v = acc[i][j] + bv[j];
            if (act == 1) v = v > 0.f ? v : 0.f;
            else if (act == 2) v = v > 0.f ? v : (expf(v) - 1.f);
            o[j] = v;
        }
        float* crow = C + (size_t)gm * N + nbase + tx * 8;
        *(float4*)&crow[0] = make_float4(o[0], o[1], o[2], o[3]);
        *(float4*)&crow[4] = make_float4(o[4], o[5], o[6], o[7]);
    }
}

static inline void sgemm128(const float* A, const float* B, const float* bias,
                            float* C, int M, int N, int K, int act) {
    dim3 g(N / 128, (M + 127) / 128);
    sgemm2_kernel<128, 8><<<g, 256>>>(A, B, bias, C, M, N, K, act);
}
static inline void sgemm64(const float* A, const float* B, const float* bias,
                           float* C, int M, int N, int K, int act) {
    dim3 g(N / 128, (M + 63) / 64);
    sgemm2_kernel<64, 4><<<g, 256>>>(A, B, bias, C, M, N, K, act);
}

// ------------------------- padding kernels -------------------------
__global__ void pad_cellx_kernel(const float* __restrict__ src, float* __restrict__ dst) {
    int i = blockIdx.x * blockDim.x + threadIdx.x;
    if (i >= NC * FCP) return;
    int r = i / FCP, k = i - r * FCP;
    dst[i] = (k < FC) ? src[(size_t)r * FC + k] : 0.f;
}
__global__ void pad_w1_kernel(const float* __restrict__ src, float* __restrict__ dst) {
    int i = blockIdx.x * blockDim.x + threadIdx.x;
    if (i >= FCP * 1024) return;
    int k = i >> 10;
    dst[i] = (k < FC) ? src[i] : 0.f;   // same layout for k < FC
}

// ------------------------- CSR build -------------------------
__global__ void hist_kernel(const int* __restrict__ ei, int E, int n, int* __restrict__ cnt) {
    int i = blockIdx.x * blockDim.x + threadIdx.x;
    if (i >= E + n) return;
    int d = (i < E) ? ei[E + i] : (i - E);
    atomicAdd(&cnt[d], 1);
}

__global__ void scan_block_kernel(const int* __restrict__ cnt, int* __restrict__ off,
                                  int* __restrict__ bsum, int n) {
    __shared__ int sh[1024];
    int t = threadIdx.x;
    int i = blockIdx.x * 1024 + t;
    int v = (i < n) ? cnt[i] : 0;
    sh[t] = v;
    __syncthreads();
    for (int o = 1; o < 1024; o <<= 1) {
        int x = (t >= o) ? sh[t - o] : 0;
        __syncthreads();
        sh[t] += x;
        __syncthreads();
    }
    if (i < n) off[i] = sh[t] - v;          // exclusive
    if (t == 1023) bsum[blockIdx.x] = sh[t];
}

__global__ void scan_add_kernel(int* __restrict__ off, const int* __restrict__ bsum,
                                int nblocks, int n, int total) {
    __shared__ int pre[64];
    if (threadIdx.x == 0) {
        int s = 0;
        for (int b = 0; b < nblocks; b++) { pre[b] = s; s += bsum[b]; }
    }
    __syncthreads();
    int i = blockIdx.x * blockDim.x + threadIdx.x;
    if (i < n) off[i] += pre[i >> 10];
    if (i == 0) off[n] = total;
}

__global__ void scatter_kernel(const int* __restrict__ ei, int E, int n,
                               const int* __restrict__ off, int* __restrict__ fill,
                               int* __restrict__ csrc) {
    int i = blockIdx.x * blockDim.x + threadIdx.x;
    if (i >= E + n) return;
    int s, d;
    if (i < E) { s = ei[i]; d = ei[E + i]; } else { s = d = i - E; }
    int pos = off[d] + atomicAdd(&fill[d], 1);
    csrc[pos] = s;
}

// ------------------------- GAT pieces -------------------------
__global__ void node_dots_kernel(const float* __restrict__ x,
                                 const float* __restrict__ asrc,
                                 const float* __restrict__ adst,
                                 float* __restrict__ out_s, float* __restrict__ out_d,
                                 int n, int F) {
    int w = (int)((blockIdx.x * (size_t)blockDim.x + threadIdx.x) >> 5);
    int lane = threadIdx.x & 31;
    if (w >= n) return;
    const float* xr = x + (size_t)w * F;
    float s = 0.f, d = 0.f;
    for (int f = lane; f < F; f += 32) {
        float v = xr[f];
        s = fmaf(v, asrc[f], s);
        d = fmaf(v, adst[f], d);
    }
#pragma unroll
    for (int o = 16; o; o >>= 1) {
        s += __shfl_xor_sync(0xffffffffu, s, o);
        d += __shfl_xor_sync(0xffffffffu, d, o);
    }
    if (lane == 0) { out_s[w] = s; out_d[w] = d; }
}

// warp-per-node segment softmax over CSR edges; writes normalized alpha
__global__ void csr_softmax_kernel(const int* __restrict__ off, const int* __restrict__ csrc,
                                   const float* __restrict__ as_, const float* __restrict__ ad_,
                                   float* __restrict__ alpha, int n) {
    int w = (int)((blockIdx.x * (size_t)blockDim.x + threadIdx.x) >> 5);
    int lane = threadIdx.x & 31;
    if (w >= n) return;
    int beg = off[w], end = off[w + 1];
    float add = ad_[w];
    float m = -1e30f;
    for (int j = beg + lane; j < end; j += 32) {
        float e = as_[csrc[j]] + add;
        e = e > 0.f ? e : 0.2f * e;
        m = fmaxf(m, e);
    }
#pragma unroll
    for (int o = 16; o; o >>= 1) m = fmaxf(m, __shfl_xor_sync(0xffffffffu, m, o));
    float s = 0.f;
    for (int j = beg + lane; j < end; j += 32) {
        float e = as_[csrc[j]] + add;
        e = e > 0.f ? e : 0.2f * e;
        float v = expf(e - m);
        alpha[j] = v;
        s += v;
    }
#pragma unroll
    for (int o = 16; o; o >>= 1) s += __shfl_xor_sync(0xffffffffu, s, o);
    float inv = 1.f / s;
    for (int j = beg + lane; j < end; j += 32) alpha[j] *= inv;
}

// block-per-node gather: out[d,:] = relu(sum_e alpha[e]*x[src[e],:] + bias)
template<int F>
__global__ void csr_gather_kernel(const int* __restrict__ off, const int* __restrict__ csrc,
                                  const float* __restrict__ alpha,
                                  const float* __restrict__ x,
                                  const float* __restrict__ bias,
                                  float* __restrict__ out) {
    constexpr int FPT = F / 256;
    int d = blockIdx.x;
    int t = threadIdx.x;
    int beg = off[d], end = off[d + 1];
    float acc[FPT];
#pragma unroll
    for (int q = 0; q < FPT; q++) acc[q] = 0.f;

    int j = beg;
    for (; j + 1 < end; j += 2) {
        int s0 = csrc[j], s1 = csrc[j + 1];
        float a0 = alpha[j], a1 = alpha[j + 1];
        const float* x0 = x + (size_t)s0 * F;
        const float* x1 = x + (size_t)s1 * F;
#pragma unroll
        for (int q = 0; q < FPT; q++)
            acc[q] = fmaf(a1, x1[t + q * 256], fmaf(a0, x0[t + q * 256], acc[q]));
    }
    if (j < end) {
        int s0 = csrc[j];
        float a0 = alpha[j];
        const float* x0 = x + (size_t)s0 * F;
#pragma unroll
        for (int q = 0; q < FPT; q++)
            acc[q] = fmaf(a0, x0[t + q * 256], acc[q]);
    }
    float* orow = out + (size_t)d * F;
#pragma unroll
    for (int q = 0; q < FPT; q++) {
        float v = acc[q] + bias[t + q * 256];
        orow[t + q * 256] = v > 0.f ? v : 0.f;
    }
}

// ------------------------- misc -------------------------
__global__ void gather_comb_kernel(const float* __restrict__ dsrc, const float* __restrict__ csrc,
                                   const int* __restrict__ di, const int* __restrict__ ci,
                                   float* __restrict__ comb) {
    int b = blockIdx.x;
    int t = threadIdx.x;
    comb[(size_t)b * 512 + t] = dsrc[(size_t)di[b] * 256 + t];
    comb[(size_t)b * 512 + 256 + t] = csrc[(size_t)ci[b] * 256 + t];
}

__global__ void head_final_kernel(const float* __restrict__ h, const float* __restrict__ W,
                                  const float* __restrict__ b, float* __restrict__ out) {
    size_t gt = blockIdx.x * (size_t)blockDim.x + threadIdx.x;
    int r = (int)(gt >> 5);
    int lane = threadIdx.x & 31;
    if (r >= BATCH) return;
    const float* hr = h + (size_t)r * 512;
    float s = 0.f;
    for (int f = lane; f < 512; f += 32) s = fmaf(hr[f], W[f], s);
#pragma unroll
    for (int o = 16; o; o >>= 1) s += __shfl_xor_sync(0xffffffffu, s, o);
    if (lane == 0) out[r] = s + b[0];
}

// ------------------------- host side -------------------------
static void build_csr(const int* ei, int E, int n, int* cnt, int* off, int* bsum, int* csrc) {
    cudaMemsetAsync(cnt, 0, n * sizeof(int));
    int total = E + n;
    hist_kernel<<<(total + 255) / 256, 256>>>(ei, E, n, cnt);
    int nblocks = (n + 1023) / 1024;
    scan_block_kernel<<<nblocks, 1024>>>(cnt, off, bsum, n);
    scan_add_kernel<<<(n + 255) / 256, 256>>>(off, bsum, nblocks, n, total);
    cudaMemsetAsync(cnt, 0, n * sizeof(int));
    scatter_kernel<<<(total + 255) / 256, 256>>>(ei, E, n, off, cnt, csrc);
}

static void run_gat_csr(const int* off, const int* csrc, int n, int F,
                        const float* x, const float* avec_s, const float* avec_d,
                        const float* bias, float* as_, float* ad_, float* alpha, float* out) {
    size_t threads = (size_t)n * 32;
    node_dots_kernel<<<(unsigned)((threads + 255) / 256), 256>>>(x, avec_s, avec_d, as_, ad_, n, F);
    csr_softmax_kernel<<<(unsigned)((threads + 255) / 256), 256>>>(off, csrc, as_, ad_, alpha, n);
    if (F == 1024)
        csr_gather_kernel<1024><<<n, 256>>>(off, csrc, alpha, x, bias, out);
    else
        csr_gather_kernel<256><<<n, 256>>>(off, csrc, alpha, x, bias, out);
}

extern "C" void kernel_launch(void* const* d_in, const int* in_sizes, int n_in,
                              void* d_out, int out_size) {
    const float* drug_x = (const float*)d_in[0];
    const float* cell_x = (const float*)d_in[1];
    const int* dei = (const int*)d_in[2];
    const int* cei = (const int*)d_in[3];
    const int* didx = (const int*)d_in[4];
    const int* cidx = (const int*)d_in[5];
    const float* dW1 = (const float*)d_in[6];  const float* db1 = (const float*)d_in[7];
    const float* cW1 = (const float*)d_in[8];  const float* cb1 = (const float*)d_in[9];
    const float* cW2 = (const float*)d_in[10]; const float* cb2 = (const float*)d_in[11];
    const float* gdW = (const float*)d_in[12]; const float* gdas = (const float*)d_in[13];
    const float* gdad = (const float*)d_in[14]; const float* gdb = (const float*)d_in[15];
    const float* g1W = (const float*)d_in[16]; const float* g1as = (const float*)d_in[17];
    const float* g1ad = (const float*)d_in[18]; const float* g1b = (const float*)d_in[19];
    const float* g2W = (const float*)d_in[20]; const float* g2as = (const float*)d_in[21];
    const float* g2ad = (const float*)d_in[22]; const float* g2b = (const float*)d_in[23];
    const float* rW1 = (const float*)d_in[24]; const float* rb1 = (const float*)d_in[25];
    const float* rW2 = (const float*)d_in[26]; const float* rb2 = (const float*)d_in[27];
    const float* rW3 = (const float*)d_in[28]; const float* rb3 = (const float*)d_in[29];
    float* out = (float*)d_out;

    float *p_d0, *p_dx, *p_dagg, *p_c0, *p_c1, *p_cx1, *p_cagg1, *p_cx2, *p_cagg2;
    float *p_as, *p_ad, *p_alpha, *p_cxp, *p_w1p, *p_comb, *p_h1, *p_h2;
    int *p_off, *p_cnt, *p_bsum, *p_csrc;
    cudaGetSymbolAddress((void**)&p_d0, g_d0);
    cudaGetSymbolAddress((void**)&p_dx, g_dx);
    cudaGetSymbolAddress((void**)&p_dagg, g_dagg);
    cudaGetSymbolAddress((void**)&p_c0, g_c0);
    cudaGetSymbolAddress((void**)&p_c1, g_c1);
    cudaGetSymbolAddress((void**)&p_cx1, g_cx1);
    cudaGetSymbolAddress((void**)&p_cagg1, g_cagg1);
    cudaGetSymbolAddress((void**)&p_cx2, g_cx2);
    cudaGetSymbolAddress((void**)&p_cagg2, g_cagg2);
    cudaGetSymbolAddress((void**)&p_as, g_as);
    cudaGetSymbolAddress((void**)&p_ad, g_ad);
    cudaGetSymbolAddress((void**)&p_alpha, g_alpha);
    cudaGetSymbolAddress((void**)&p_off, g_off);
    cudaGetSymbolAddress((void**)&p_cnt, g_cnt);
    cudaGetSymbolAddress((void**)&p_bsum, g_bsum);
    cudaGetSymbolAddress((void**)&p_csrc, g_csrc);
    cudaGetSymbolAddress((void**)&p_cxp, g_cxp);
    cudaGetSymbolAddress((void**)&p_w1p, g_w1p);
    cudaGetSymbolAddress((void**)&p_comb, g_comb);
    cudaGetSymbolAddress((void**)&p_h1, g_h1);
    cudaGetSymbolAddress((void**)&p_h2, g_h2);

    // ---- padding for K=735 GEMM ----
    pad_cellx_kernel<<<(NC * FCP + 255) / 256, 256>>>(cell_x, p_cxp);
    pad_w1_kernel<<<(FCP * 1024 + 255) / 256, 256>>>(cW1, p_w1p);

    // ---- feature transforms ----
    sgemm128(drug_x, dW1, db1, p_d0, ND, 256, FD, 1);
    sgemm128(p_cxp, p_w1p, cb1, p_c0, NC, 1024, FCP, 1);
    sgemm64(p_c0, cW2, cb2, p_c1, NC, 256, 1024, 1);

    // ---- drug GAT (256 -> 256) ----
    sgemm128(p_d0, gdW, nullptr, p_dx, ND, 256, 256, 0);
    build_csr(dei, ED, ND, p_cnt, p_off, p_bsum, p_csrc);
    run_gat_csr(p_off, p_csrc, ND, 256, p_dx, gdas, gdad, gdb, p_as, p_ad, p_alpha, p_dagg);

    // ---- cell GAT1 (256 -> 1024) ----
    sgemm128(p_c1, g1W, nullptr, p_cx1, NC, 1024, 256, 0);
    build_csr(cei, EC, NC, p_cnt, p_off, p_bsum, p_csrc);   // shared by GAT1 + GAT2
    run_gat_csr(p_off, p_csrc, NC, 1024, p_cx1, g1as, g1ad, g1b, p_as, p_ad, p_alpha, p_cagg1);

    // ---- cell GAT2 (1024 -> 256) ----
    sgemm64(p_cagg1, g2W, nullptr, p_cx2, NC, 256, 1024, 0);
    run_gat_csr(p_off, p_csrc, NC, 256, p_cx2, g2as, g2ad, g2b, p_as, p_ad, p_alpha, p_cagg2);

    // ---- pair gather + regression head ----
    gather_comb_kernel<<<BATCH, 256>>>(p_dagg, p_cagg2, didx, cidx, p_comb);
    sgemm128(p_comb, rW1, rb1, p_h1, BATCH, 512, 512, 2);
    sgemm128(p_h1, rW2, rb2, p_h2, BATCH, 512, 512, 2);
    head_final_kernel<<<(BATCH * 32 + 255) / 256, 256>>>(p_h2, rW3, rb3, out);
}

// round 12
// speedup vs baseline: 1.4572x; 1.3929x over previous
#include <cuda_runtime.h>
#include <math.h>
#include <stdint.h>

// Problem dims (fixed by setup_inputs)
#define ND 50000
#define FD 128
#define NC 10000
#define FC 735
#define FCP 736        // padded K for cell MLP1
#define ED 800000
#define EC 160000
#define BATCH 16384

// ------------------------- scratch (device globals) -------------------------
__device__ float g_d0[ND * 256];
__device__ float g_dx[ND * 256];
__device__ float g_dagg[ND * 256];
__device__ float g_c0[NC * 1024];
__device__ float g_c1[NC * 256];
__device__ float g_cx1[NC * 1024];
__device__ float g_cagg1[NC * 1024];
__device__ float g_cx2[NC * 256];
__device__ float g_cagg2[NC * 256];
__device__ float g_as[ND];
__device__ float g_ad[ND];
__device__ float g_alpha[ED + ND];
__device__ int   g_off[ND + 1];
__device__ int   g_cnt[ND];
__device__ int   g_bsum[64];
__device__ int   g_csrc[ED + ND];
__device__ float g_cxp[NC * FCP];
__device__ float g_w1p[FCP * 1024];
__device__ float g_comb[BATCH * 512];
__device__ float g_h1[BATCH * 512];
__device__ float g_h2[BATCH * 512];

// ------------------------- helpers -------------------------
#define SW128(x) ((x) ^ (((x) >> 3) & 0x70))

__device__ __forceinline__ void mma_tf32(float* c, const uint32_t* a, const uint32_t* b) {
    asm volatile("mma.sync.aligned.m16n8k8.row.col.f32.tf32.tf32.f32 "
                 "{%0,%1,%2,%3},{%4,%5,%6,%7},{%8,%9},{%0,%1,%2,%3};"
                 : "+f"(c[0]), "+f"(c[1]), "+f"(c[2]), "+f"(c[3])
                 : "r"(a[0]), "r"(a[1]), "r"(a[2]), "r"(a[3]),
                   "r"(b[0]), "r"(b[1]));
}
__device__ __forceinline__ void split2(float v, uint32_t& hi, uint32_t& lo) {
    uint32_t h;
    asm("cvt.rna.tf32.f32 %0, %1;" : "=r"(h) : "f"(v));
    hi = h;
    lo = __float_as_uint(v - __uint_as_float(h));
}
__device__ __forceinline__ void cp16(uint32_t dst, const float* src, int sz) {
    asm volatile("cp.async.cg.shared.global [%0], [%1], 16, %2;"
                 :: "r"(dst), "l"(src), "r"(sz) : "memory");
}

// ------------------------- tf32 mma.sync GEMM -------------------------
// C[M,N] = act(A@B + bias); A [M,K], B [K,N] row-major. BM=BN=128, BK=32.
// Requires K%32==0, N%128==0. 3xTF32 split for fp32-level accuracy.
// smem/stage: A 16KB ([m][k] 128B rows, SW128) + B 16KB ([k][n] 512B rows, XOR swz)
#define STAGE 32768
#define NPIPE 3
#define GEMM_SMEM (NPIPE * STAGE)

__global__ void __launch_bounds__(256, 2)
mma_gemm_kernel(const float* __restrict__ A, const float* __restrict__ B,
                const float* __restrict__ bias, float* __restrict__ C,
                int M, int N, int K, int act) {
    extern __shared__ char smem[];
    const int tid = threadIdx.x;
    const int wid = tid >> 5, lane = tid & 31;
    const int gq = lane >> 2, tg = lane & 3;       // quad row / thread-in-quad
    const int warp_m = wid & 3, warp_n = wid >> 2; // 4x2 warp grid
    const int mbase = blockIdx.y * 128, nbase = blockIdx.x * 128;
    const uint32_t smem_b32 = (uint32_t)__cvta_generic_to_shared(smem);

    const int nk = K >> 5;

    // ---- stage loader (all 256 threads) ----
    auto load_stage = [&](int ci) {
        const uint32_t sb = smem_b32 + (ci % NPIPE) * STAGE;
        const int k0 = ci << 5;
        // A: 128 rows x 32 floats (128B rows, SW128)
#pragma unroll
        for (int p = 0; p < 4; p++) {
            int uid = tid + p * 256;
            int row = uid >> 3, q = uid & 7;
            int gm = mbase + row;
            const float* src = A + (size_t)(gm < M ? gm : 0) * K + k0 + q * 4;
            cp16(sb + SW128((uint32_t)(row * 128 + q * 16)), src, (gm < M) ? 16 : 0);
        }
        // B: 32 k-rows x 128 floats (512B rows), unit ^= (k&3)<<1
#pragma unroll
        for (int p = 0; p < 4; p++) {
            int uid = tid + p * 256;
            int k = uid >> 5, un = uid & 31;
            const float* src = B + (size_t)(k0 + k) * N + nbase + un * 4;
            uint32_t dst = sb + 16384 + k * 512 + ((un ^ ((k & 3) << 1)) << 4);
            cp16(dst, src, 16);
        }
    };

    // prologue: stages 0,1
    load_stage(0);
    asm volatile("cp.async.commit_group;" ::: "memory");
    load_stage(1);
    asm volatile("cp.async.commit_group;" ::: "memory");

    float c[2][8][4];
#pragma unroll
    for (int mt = 0; mt < 2; mt++)
#pragma unroll
        for (int nt = 0; nt < 8; nt++)
#pragma unroll
            for (int j = 0; j < 4; j++) c[mt][nt][j] = 0.f;

    const int t2 = tg << 1;

    for (int t = 0; t < nk; t++) {
        int ci = t + 2;
        if (ci < nk) load_stage(ci);
        asm volatile("cp.async.commit_group;" ::: "memory");
        asm volatile("cp.async.wait_group 2;" ::: "memory");
        __syncthreads();

        const char* aS = smem + (t % NPIPE) * STAGE;
        const char* bS = aS + 16384;

#pragma unroll
        for (int step = 0; step < 4; step++) {
            const int k0s = step * 8;
            // A fragments (hi/lo)
            uint32_t ah[2][4], al[2][4];
#pragma unroll
            for (int mt = 0; mt < 2; mt++) {
                int r0 = warp_m * 32 + mt * 16 + gq;
#pragma unroll
                for (int j = 0; j < 4; j++) {
                    int r = r0 + ((j & 1) ? 8 : 0);
                    int k = k0s + tg + ((j & 2) ? 4 : 0);
                    float v = *(const float*)(aS + SW128((uint32_t)(r * 128 + k * 4)));
                    split2(v, ah[mt][j], al[mt][j]);
                }
            }
            // B fragments in halves of 4 n-tiles (register pressure)
#pragma unroll
            for (int half = 0; half < 2; half++) {
                uint32_t bh[4][2], bl[4][2];
#pragma unroll
                for (int j = 0; j < 4; j++) {
                    int nt = half * 4 + j;
                    int n = warp_n * 64 + nt * 8 + gq;
                    int unit_base = n >> 2, nb = (n & 3) * 4;
#pragma unroll
                    for (int rr = 0; rr < 2; rr++) {
                        int k = k0s + tg + rr * 4;
                        uint32_t phys = (uint32_t)(k * 512 + ((unit_base ^ t2) << 4) + nb);
                        float v = *(const float*)(bS + phys);
                        split2(v, bh[j][rr], bl[j][rr]);
                    }
                }
#pragma unroll
                for (int mt = 0; mt < 2; mt++)
#pragma unroll
                    for (int j = 0; j < 4; j++) {
                        float* cc = c[mt][half * 4 + j];
                        mma_tf32(cc, ah[mt], bh[j]);
                        mma_tf32(cc, al[mt], bh[j]);
                        mma_tf32(cc, ah[mt], bl[j]);
                    }
            }
        }
        __syncthreads();
    }

    // ---- epilogue ----
#pragma unroll
    for (int mt = 0; mt < 2; mt++) {
        int row0 = mbase + warp_m * 32 + mt * 16 + gq;
#pragma unroll
        for (int nt = 0; nt < 8; nt++) {
            int col = nbase + warp_n * 64 + nt * 8 + 2 * tg;
            float b0 = bias ? bias[col] : 0.f;
            float b1 = bias ? bias[col + 1] : 0.f;
#pragma unroll
            for (int h = 0; h < 2; h++) {
                int row = row0 + h * 8;
                if (row >= M) continue;
                float v0 = c[mt][nt][h * 2 + 0] + b0;
                float v1 = c[mt][nt][h * 2 + 1] + b1;
                if (act == 1) {
                    v0 = v0 > 0.f ? v0 : 0.f;
                    v1 = v1 > 0.f ? v1 : 0.f;
                } else if (act == 2) {
                    v0 = v0 > 0.f ? v0 : (expf(v0) - 1.f);
                    v1 = v1 > 0.f ? v1 : (expf(v1) - 1.f);
                }
                *(float2*)&C[(size_t)row * N + col] = make_float2(v0, v1);
            }
        }
    }
}

static inline void tgemm(const float* A, const float* B, const float* bias,
                         float* C, int M, int N, int K, int act) {
    cudaFuncSetAttribute(mma_gemm_kernel,
                         cudaFuncAttributeMaxDynamicSharedMemorySize, GEMM_SMEM);
    dim3 g(N / 128, (M + 127) / 128);
    mma_gemm_kernel<<<g, 256, GEMM_SMEM>>>(A, B, bias, C, M, N, K, act);
}

// ------------------------- padding kernels -------------------------
__global__ void pad_cellx_kernel(const float* __restrict__ src, float* __restrict__ dst) {
    int i = blockIdx.x * blockDim.x + threadIdx.x;
    if (i >= NC * FCP) return;
    int r = i / FCP, k = i - r * FCP;
    dst[i] = (k < FC) ? src[(size_t)r * FC + k] : 0.f;
}
__global__ void pad_w1_kernel(const float* __restrict__ src, float* __restrict__ dst) {
    int i = blockIdx.x * blockDim.x + threadIdx.x;
    if (i >= FCP * 1024) return;
    int k = i >> 10;
    dst[i] = (k < FC) ? src[i] : 0.f;
}

// ------------------------- CSR build -------------------------
__global__ void hist_kernel(const int* __restrict__ ei, int E, int n, int* __restrict__ cnt) {
    int i = blockIdx.x * blockDim.x + threadIdx.x;
    if (i >= E + n) return;
    int d = (i < E) ? ei[E + i] : (i - E);
    atomicAdd(&cnt[d], 1);
}

__global__ void scan_block_kernel(const int* __restrict__ cnt, int* __restrict__ off,
                                  int* __restrict__ bsum, int n) {
    __shared__ int sh[1024];
    int t = threadIdx.x;
    int i = blockIdx.x * 1024 + t;
    int v = (i < n) ? cnt[i] : 0;
    sh[t] = v;
    __syncthreads();
    for (int o = 1; o < 1024; o <<= 1) {
        int x = (t >= o) ? sh[t - o] : 0;
        __syncthreads();
        sh[t] += x;
        __syncthreads();
    }
    if (i < n) off[i] = sh[t] - v;
    if (t == 1023) bsum[blockIdx.x] = sh[t];
}

__global__ void scan_add_kernel(int* __restrict__ off, const int* __restrict__ bsum,
                                int nblocks, int n, int total) {
    __shared__ int pre[64];
    if (threadIdx.x == 0) {
        int s = 0;
        for (int b = 0; b < nblocks; b++) { pre[b] = s; s += bsum[b]; }
    }
    __syncthreads();
    int i = blockIdx.x * blockDim.x + threadIdx.x;
    if (i < n) off[i] += pre[i >> 10];
    if (i == 0) off[n] = total;
}

__global__ void scatter_kernel(const int* __restrict__ ei, int E, int n,
                               const int* __restrict__ off, int* __restrict__ fill,
                               int* __restrict__ csrc) {
    int i = blockIdx.x * blockDim.x + threadIdx.x;
    if (i >= E + n) return;
    int s, d;
    if (i < E) { s = ei[i]; d = ei[E + i]; } else { s = d = i - E; }
    int pos = off[d] + atomicAdd(&fill[d], 1);
    csrc[pos] = s;
}

// ------------------------- GAT pieces -------------------------
__global__ void node_dots_kernel(const float* __restrict__ x,
                                 const float* __restrict__ asrc,
                                 const float* __restrict__ adst,
                                 float* __restrict__ out_s, float* __restrict__ out_d,
                                 int n, int F) {
    int w = (int)((blockIdx.x * (size_t)blockDim.x + threadIdx.x) >> 5);
    int lane = threadIdx.x & 31;
    if (w >= n) return;
    const float* xr = x + (size_t)w * F;
    float s = 0.f, d = 0.f;
    for (int f = lane; f < F; f += 32) {
        float v = xr[f];
        s = fmaf(v, asrc[f], s);
        d = fmaf(v, adst[f], d);
    }
#pragma unroll
    for (int o = 16; o; o >>= 1) {
        s += __shfl_xor_sync(0xffffffffu, s, o);
        d += __shfl_xor_sync(0xffffffffu, d, o);
    }
    if (lane == 0) { out_s[w] = s; out_d[w] = d; }
}

__global__ void csr_softmax_kernel(const int* __restrict__ off, const int* __restrict__ csrc,
                                   const float* __restrict__ as_, const float* __restrict__ ad_,
                                   float* __restrict__ alpha, int n) {
    int w = (int)((blockIdx.x * (size_t)blockDim.x + threadIdx.x) >> 5);
    int lane = threadIdx.x & 31;
    if (w >= n) return;
    int beg = off[w], end = off[w + 1];
    float add = ad_[w];
    float m = -1e30f;
    for (int j = beg + lane; j < end; j += 32) {
        float e = as_[csrc[j]] + add;
        e = e > 0.f ? e : 0.2f * e;
        m = fmaxf(m, e);
    }
#pragma unroll
    for (int o = 16; o; o >>= 1) m = fmaxf(m, __shfl_xor_sync(0xffffffffu, m, o));
    float s = 0.f;
    for (int j = beg + lane; j < end; j += 32) {
        float e = as_[csrc[j]] + add;
        e = e > 0.f ? e : 0.2f * e;
        float v = expf(e - m);
        alpha[j] = v;
        s += v;
    }
#pragma unroll
    for (int o = 16; o; o >>= 1) s += __shfl_xor_sync(0xffffffffu, s, o);
    float inv = 1.f / s;
    for (int j = beg + lane; j < end; j += 32) alpha[j] *= inv;
}

template<int F>
__global__ void csr_gather_kernel(const int* __restrict__ off, const int* __restrict__ csrc,
                                  const float* __restrict__ alpha,
                                  const float* __restrict__ x,
                                  const float* __restrict__ bias,
                                  float* __restrict__ out) {
    constexpr int FPT = F / 256;
    int d = blockIdx.x;
    int t = threadIdx.x;
    int beg = off[d], end = off[d + 1];
    float acc[FPT];
#pragma unroll
    for (int q = 0; q < FPT; q++) acc[q] = 0.f;

    int j = beg;
    for (; j + 1 < end; j += 2) {
        int s0 = csrc[j], s1 = csrc[j + 1];
        float a0 = alpha[j], a1 = alpha[j + 1];
        const float* x0 = x + (size_t)s0 * F;
        const float* x1 = x + (size_t)s1 * F;
#pragma unroll
        for (int q = 0; q < FPT; q++)
            acc[q] = fmaf(a1, x1[t + q * 256], fmaf(a0, x0[t + q * 256], acc[q]));
    }
    if (j < end) {
        int s0 = csrc[j];
        float a0 = alpha[j];
        const float* x0 = x + (size_t)s0 * F;
#pragma unroll
        for (int q = 0; q < FPT; q++)
            acc[q] = fmaf(a0, x0[t + q * 256], acc[q]);
    }
    float* orow = out + (size_t)d * F;
#pragma unroll
    for (int q = 0; q < FPT; q++) {
        float v = acc[q] + bias[t + q * 256];
        orow[t + q * 256] = v > 0.f ? v : 0.f;
    }
}

// ------------------------- misc -------------------------
__global__ void gather_comb_kernel(const float* __restrict__ dsrc, const float* __restrict__ csrc,
                                   const int* __restrict__ di, const int* __restrict__ ci,
                                   float* __restrict__ comb) {
    int b = blockIdx.x;
    int t = threadIdx.x;
    comb[(size_t)b * 512 + t] = dsrc[(size_t)di[b] * 256 + t];
    comb[(size_t)b * 512 + 256 + t] = csrc[(size_t)ci[b] * 256 + t];
}

__global__ void head_final_kernel(const float* __restrict__ h, const float* __restrict__ W,
                                  const float* __restrict__ b, float* __restrict__ out) {
    size_t gt = blockIdx.x * (size_t)blockDim.x + threadIdx.x;
    int r = (int)(gt >> 5);
    int lane = threadIdx.x & 31;
    if (r >= BATCH) return;
    const float* hr = h + (size_t)r * 512;
    float s = 0.f;
    for (int f = lane; f < 512; f += 32) s = fmaf(hr[f], W[f], s);
#pragma unroll
    for (int o = 16; o; o >>= 1) s += __shfl_xor_sync(0xffffffffu, s, o);
    if (lane == 0) out[r] = s + b[0];
}

// ------------------------- host side -------------------------
static void build_csr(const int* ei, int E, int n, int* cnt, int* off, int* bsum, int* csrc) {
    cudaMemsetAsync(cnt, 0, n * sizeof(int));
    int total = E + n;
    hist_kernel<<<(total + 255) / 256, 256>>>(ei, E, n, cnt);
    int nblocks = (n + 1023) / 1024;
    scan_block_kernel<<<nblocks, 1024>>>(cnt, off, bsum, n);
    scan_add_kernel<<<(n + 255) / 256, 256>>>(off, bsum, nblocks, n, total);
    cudaMemsetAsync(cnt, 0, n * sizeof(int));
    scatter_kernel<<<(total + 255) / 256, 256>>>(ei, E, n, off, cnt, csrc);
}

static void run_gat_csr(const int* off, const int* csrc, int n, int F,
                        const float* x, const float* avec_s, const float* avec_d,
                        const float* bias, float* as_, float* ad_, float* alpha, float* out) {
    size_t threads = (size_t)n * 32;
    node_dots_kernel<<<(unsigned)((threads + 255) / 256), 256>>>(x, avec_s, avec_d, as_, ad_, n, F);
    csr_softmax_kernel<<<(unsigned)((threads + 255) / 256), 256>>>(off, csrc, as_, ad_, alpha, n);
    if (F == 1024)
        csr_gather_kernel<1024><<<n, 256>>>(off, csrc, alpha, x, bias, out);
    else
        csr_gather_kernel<256><<<n, 256>>>(off, csrc, alpha, x, bias, out);
}

extern "C" void kernel_launch(void* const* d_in, const int* in_sizes, int n_in,
                              void* d_out, int out_size) {
    const float* drug_x = (const float*)d_in[0];
    const float* cell_x = (const float*)d_in[1];
    const int* dei = (const int*)d_in[2];
    const int* cei = (const int*)d_in[3];
    const int* didx = (const int*)d_in[4];
    const int* cidx = (const int*)d_in[5];
    const float* dW1 = (const float*)d_in[6];  const float* db1 = (const float*)d_in[7];
    const float* cW1 = (const float*)d_in[8];  const float* cb1 = (const float*)d_in[9];
    const float* cW2 = (const float*)d_in[10]; const float* cb2 = (const float*)d_in[11];
    const float* gdW = (const float*)d_in[12]; const float* gdas = (const float*)d_in[13];
    const float* gdad = (const float*)d_in[14]; const float* gdb = (const float*)d_in[15];
    const float* g1W = (const float*)d_in[16]; const float* g1as = (const float*)d_in[17];
    const float* g1ad = (const float*)d_in[18]; const float* g1b = (const float*)d_in[19];
    const float* g2W = (const float*)d_in[20]; const float* g2as = (const float*)d_in[21];
    const float* g2ad = (const float*)d_in[22]; const float* g2b = (const float*)d_in[23];
    const float* rW1 = (const float*)d_in[24]; const float* rb1 = (const float*)d_in[25];
    const float* rW2 = (const float*)d_in[26]; const float* rb2 = (const float*)d_in[27];
    const float* rW3 = (const float*)d_in[28]; const float* rb3 = (const float*)d_in[29];
    float* out = (float*)d_out;

    float *p_d0, *p_dx, *p_dagg, *p_c0, *p_c1, *p_cx1, *p_cagg1, *p_cx2, *p_cagg2;
    float *p_as, *p_ad, *p_alpha, *p_cxp, *p_w1p, *p_comb, *p_h1, *p_h2;
    int *p_off, *p_cnt, *p_bsum, *p_csrc;
    cudaGetSymbolAddress((void**)&p_d0, g_d0);
    cudaGetSymbolAddress((void**)&p_dx, g_dx);
    cudaGetSymbolAddress((void**)&p_dagg, g_dagg);
    cudaGetSymbolAddress((void**)&p_c0, g_c0);
    cudaGetSymbolAddress((void**)&p_c1, g_c1);
    cudaGetSymbolAddress((void**)&p_cx1, g_cx1);
    cudaGetSymbolAddress((void**)&p_cagg1, g_cagg1);
    cudaGetSymbolAddress((void**)&p_cx2, g_cx2);
    cudaGetSymbolAddress((void**)&p_cagg2, g_cagg2);
    cudaGetSymbolAddress((void**)&p_as, g_as);
    cudaGetSymbolAddress((void**)&p_ad, g_ad);
    cudaGetSymbolAddress((void**)&p_alpha, g_alpha);
    cudaGetSymbolAddress((void**)&p_off, g_off);
    cudaGetSymbolAddress((void**)&p_cnt, g_cnt);
    cudaGetSymbolAddress((void**)&p_bsum, g_bsum);
    cudaGetSymbolAddress((void**)&p_csrc, g_csrc);
    cudaGetSymbolAddress((void**)&p_cxp, g_cxp);
    cudaGetSymbolAddress((void**)&p_w1p, g_w1p);
    cudaGetSymbolAddress((void**)&p_comb, g_comb);
    cudaGetSymbolAddress((void**)&p_h1, g_h1);
    cudaGetSymbolAddress((void**)&p_h2, g_h2);

    // ---- padding for K=735 GEMM ----
    pad_cellx_kernel<<<(NC * FCP + 255) / 256, 256>>>(cell_x, p_cxp);
    pad_w1_kernel<<<(FCP * 1024 + 255) / 256, 256>>>(cW1, p_w1p);

    // ---- feature transforms ----
    tgemm(drug_x, dW1, db1, p_d0, ND, 256, FD, 1);
    tgemm(p_cxp, p_w1p, cb1, p_c0, NC, 1024, FCP, 1);
    tgemm(p_c0, cW2, cb2, p_c1, NC, 256, 1024, 1);

    // ---- drug GAT (256 -> 256) ----
    tgemm(p_d0, gdW, nullptr, p_dx, ND, 256, 256, 0);
    build_csr(dei, ED, ND, p_cnt, p_off, p_bsum, p_csrc);
    run_gat_csr(p_off, p_csrc, ND, 256, p_dx, gdas, gdad, gdb, p_as, p_ad, p_alpha, p_dagg);

    // ---- cell GAT1 (256 -> 1024) ----
    tgemm(p_c1, g1W, nullptr, p_cx1, NC, 1024, 256, 0);
    build_csr(cei, EC, NC, p_cnt, p_off, p_bsum, p_csrc);   // shared by GAT1 + GAT2
    run_gat_csr(p_off, p_csrc, NC, 1024, p_cx1, g1as, g1ad, g1b, p_as, p_ad, p_alpha, p_cagg1);

    // ---- cell GAT2 (1024 -> 256) ----
    tgemm(p_cagg1, g2W, nullptr, p_cx2, NC, 256, 1024, 0);
    run_gat_csr(p_off, p_csrc, NC, 256, p_cx2, g2as, g2ad, g2b, p_as, p_ad, p_alpha, p_cagg2);

    // ---- pair gather + regression head ----
    gather_comb_kernel<<<BATCH, 256>>>(p_dagg, p_cagg2, didx, cidx, p_comb);
    tgemm(p_comb, rW1, rb1, p_h1, BATCH, 512, 512, 2);
    tgemm(p_h1, rW2, rb2, p_h2, BATCH, 512, 512, 2);
    head_final_kernel<<<(BATCH * 32 + 255) / 256, 256>>>(p_h2, rW3, rb3, out);
}

// round 13
// speedup vs baseline: 2.2255x; 1.5272x over previous
#include <cuda_runtime.h>
#include <cuda_bf16.h>
#include <math.h>
#include <stdint.h>

// Problem dims (fixed by setup_inputs)
#define ND 50000
#define FD 128
#define NC 10000
#define FC 735
#define FCP 736        // padded K for cell MLP1
#define ED 800000
#define EC 160000
#define BATCH 16384

typedef __nv_bfloat16 bf16;
typedef __nv_bfloat162 bf162;

// ------------------------- scratch (device globals) -------------------------
// fp32 tensors (consumed by non-GEMM kernels)
__device__ float g_dx[ND * 256];
__device__ float g_dagg[ND * 256];
__device__ float g_cx1[NC * 1024];
__device__ float g_cx2[NC * 256];
__device__ float g_cagg2[NC * 256];
__device__ float g_h2[BATCH * 512];
__device__ float g_as[ND];
__device__ float g_ad[ND];
__device__ float g_alpha[ED + ND];
__device__ int   g_off[ND + 1];
__device__ int   g_cnt[ND];
__device__ int   g_bsum[64];
__device__ int   g_csrc[ED + ND];
// bf16 hi/lo activation tensors (GEMM inputs)
__device__ bf16 g_axh[ND * FD],    g_axl[ND * FD];      // drug_x split
__device__ bf16 g_cxh[NC * FCP],   g_cxl[NC * FCP];     // cell_x padded split
__device__ bf16 g_d0h[ND * 256],   g_d0l[ND * 256];
__device__ bf16 g_c0h[NC * 1024],  g_c0l[NC * 1024];
__device__ bf16 g_c1h[NC * 256],   g_c1l[NC * 256];
__device__ bf16 g_ca1h[NC * 1024], g_ca1l[NC * 1024];
__device__ bf16 g_cmh[BATCH * 512], g_cml[BATCH * 512];
__device__ bf16 g_h1h[BATCH * 512], g_h1l[BATCH * 512];
// bf16 hi/lo transposed weights [N,K]
__device__ bf16 g_wd1h[256 * 128],  g_wd1l[256 * 128];
__device__ bf16 g_w1h[1024 * FCP],  g_w1l[1024 * FCP];
__device__ bf16 g_w2h[256 * 1024],  g_w2l[256 * 1024];
__device__ bf16 g_wgdh[256 * 256],  g_wgdl[256 * 256];
__device__ bf16 g_wg1h[1024 * 256], g_wg1l[1024 * 256];
__device__ bf16 g_wg2h[256 * 1024], g_wg2l[256 * 1024];
__device__ bf16 g_wr1h[512 * 512],  g_wr1l[512 * 512];
__device__ bf16 g_wr2h[512 * 512],  g_wr2l[512 * 512];

// ------------------------- helpers -------------------------
#define SW128(x) ((x) ^ (((x) >> 3) & 0x70))

__device__ __forceinline__ void bsplit(float v, bf16& h, bf16& l) {
    h = __float2bfloat16_rn(v);
    l = __float2bfloat16_rn(v - __bfloat162float(h));
}
__device__ __forceinline__ void mma_bf16(float* c, const uint32_t* a, const uint32_t* b) {
    asm volatile("mma.sync.aligned.m16n8k16.row.col.f32.bf16.bf16.f32 "
                 "{%0,%1,%2,%3},{%4,%5,%6,%7},{%8,%9},{%0,%1,%2,%3};"
                 : "+f"(c[0]), "+f"(c[1]), "+f"(c[2]), "+f"(c[3])
                 : "r"(a[0]), "r"(a[1]), "r"(a[2]), "r"(a[3]),
                   "r"(b[0]), "r"(b[1]));
}
__device__ __forceinline__ void cp16(uint32_t dst, const void* src, int sz) {
    asm volatile("cp.async.cg.shared.global [%0], [%1], 16, %2;"
                 :: "r"(dst), "l"(src), "r"(sz) : "memory");
}

// ------------------------- bf16x2 tensor-core GEMM -------------------------
// C[M,N] = act(A@B + bias); A given as hi/lo bf16 [M,K]; B as hi/lo bf16 [N,K]
// (pre-transposed). K%32==0, N%128==0. acc = Ah*Bh + Al*Bh + Ah*Bl (fp32 accum).
// hl_out=0: C fp32 [M,N]. hl_out=1: C = bf16 hi [M,N] followed by bf16 lo [M,N].
#define STAGE 32768
#define NPIPE 3
#define GEMM_SMEM (NPIPE * STAGE)

__global__ void __launch_bounds__(256, 2)
bgemm_kernel(const bf16* __restrict__ Ah, const bf16* __restrict__ Al,
             const bf16* __restrict__ Bh, const bf16* __restrict__ Bl,
             const float* __restrict__ bias, void* __restrict__ Cp,
             int M, int N, int K, int act, int hl_out) {
    extern __shared__ char smem[];
    const int tid = threadIdx.x;
    const int wid = tid >> 5, lane = tid & 31;
    const int gq = lane >> 2, tg = lane & 3;
    const int warp_m = wid & 3, warp_n = wid >> 2;   // 4x2 warp grid, tile 32x64
    const int mbase = blockIdx.y * 128, nbase = blockIdx.x * 128;
    const uint32_t sB = (uint32_t)__cvta_generic_to_shared(smem);

    const int nk = K >> 5;

    // stage layout: A [128 rows][128B: hi k0..31 | lo k0..31], B same with n rows
    auto load_stage = [&](int ci) {
        const uint32_t sb = sB + (ci % NPIPE) * STAGE;
        const int k0 = ci << 5;
#pragma unroll
        for (int p = 0; p < 4; p++) {
            int uid = tid + p * 256;
            int row = uid >> 3, u = uid & 7;
            int gm = mbase + row;
            const bf16* src = (u < 4 ? Ah : Al) + (size_t)(gm < M ? gm : 0) * K + k0 + (u & 3) * 8;
            cp16(sb + SW128((uint32_t)(row * 128 + u * 16)), src, (gm < M) ? 16 : 0);
        }
#pragma unroll
        for (int p = 0; p < 4; p++) {
            int uid = tid + p * 256;
            int row = uid >> 3, u = uid & 7;
            const bf16* src = (u < 4 ? Bh : Bl) + (size_t)(nbase + row) * K + k0 + (u & 3) * 8;
            cp16(sb + 16384 + SW128((uint32_t)(row * 128 + u * 16)), src, 16);
        }
    };

    load_stage(0);
    asm volatile("cp.async.commit_group;" ::: "memory");
    load_stage(1);
    asm volatile("cp.async.commit_group;" ::: "memory");

    float c[2][8][4];
#pragma unroll
    for (int mt = 0; mt < 2; mt++)
#pragma unroll
        for (int nt = 0; nt < 8; nt++)
#pragma unroll
            for (int j = 0; j < 4; j++) c[mt][nt][j] = 0.f;

    for (int t = 0; t < nk; t++) {
        if (t + 2 < nk) load_stage(t + 2);
        asm volatile("cp.async.commit_group;" ::: "memory");
        asm volatile("cp.async.wait_group 2;" ::: "memory");
        __syncthreads();

        const char* aS = smem + (t % NPIPE) * STAGE;
        const char* bS = aS + 16384;

#pragma unroll
        for (int s = 0; s < 2; s++) {
            // A fragments: af[mt][h][4]
            uint32_t af[2][2][4];
#pragma unroll
            for (int mt = 0; mt < 2; mt++) {
                int r0 = warp_m * 32 + mt * 16 + gq;
#pragma unroll
                for (int h = 0; h < 2; h++) {
                    uint32_t c0 = (uint32_t)(h * 64 + s * 32 + tg * 4);
                    af[mt][h][0] = *(const uint32_t*)(aS + SW128((uint32_t)(r0 * 128) + c0));
                    af[mt][h][1] = *(const uint32_t*)(aS + SW128((uint32_t)((r0 + 8) * 128) + c0));
                    af[mt][h][2] = *(const uint32_t*)(aS + SW128((uint32_t)(r0 * 128) + c0 + 16));
                    af[mt][h][3] = *(const uint32_t*)(aS + SW128((uint32_t)((r0 + 8) * 128) + c0 + 16));
                }
            }
#pragma unroll
            for (int nt = 0; nt < 8; nt++) {
                int n = warp_n * 64 + nt * 8 + gq;
                uint32_t bfr[2][2];
#pragma unroll
                for (int h = 0; h < 2; h++) {
                    uint32_t c0 = (uint32_t)(h * 64 + s * 32 + tg * 4);
                    bfr[h][0] = *(const uint32_t*)(bS + SW128((uint32_t)(n * 128) + c0));
                    bfr[h][1] = *(const uint32_t*)(bS + SW128((uint32_t)(n * 128) + c0 + 16));
                }
#pragma unroll
                for (int mt = 0; mt < 2; mt++) {
                    float* cc = c[mt][nt];
                    mma_bf16(cc, af[mt][0], bfr[0]);   // hi*hi
                    mma_bf16(cc, af[mt][1], bfr[0]);   // lo*hi
                    mma_bf16(cc, af[mt][0], bfr[1]);   // hi*lo
                }
            }
        }
        __syncthreads();
    }

    // ---- epilogue ----
#pragma unroll
    for (int mt = 0; mt < 2; mt++) {
        int row0 = mbase + warp_m * 32 + mt * 16 + gq;
#pragma unroll
        for (int nt = 0; nt < 8; nt++) {
            int col = nbase + warp_n * 64 + nt * 8 + 2 * tg;
            float b0 = bias ? bias[col] : 0.f;
            float b1 = bias ? bias[col + 1] : 0.f;
#pragma unroll
            for (int h = 0; h < 2; h++) {
                int row = row0 + h * 8;
                if (row >= M) continue;
                float v0 = c[mt][nt][h * 2 + 0] + b0;
                float v1 = c[mt][nt][h * 2 + 1] + b1;
                if (act == 1) {
                    v0 = v0 > 0.f ? v0 : 0.f;
                    v1 = v1 > 0.f ? v1 : 0.f;
                } else if (act == 2) {
                    v0 = v0 > 0.f ? v0 : (expf(v0) - 1.f);
                    v1 = v1 > 0.f ? v1 : (expf(v1) - 1.f);
                }
                if (!hl_out) {
                    *(float2*)((float*)Cp + (size_t)row * N + col) = make_float2(v0, v1);
                } else {
                    bf16* Ch = (bf16*)Cp;
                    bf16* Cl = Ch + (size_t)M * N;
                    bf16 h0, l0, h1, l1;
                    bsplit(v0, h0, l0);
                    bsplit(v1, h1, l1);
                    bf162 hv; hv.x = h0; hv.y = h1;
                    bf162 lv; lv.x = l0; lv.y = l1;
                    *(bf162*)&Ch[(size_t)row * N + col] = hv;
                    *(bf162*)&Cl[(size_t)row * N + col] = lv;
                }
            }
        }
    }
}

static inline void bgemm(const bf16* Ah, const bf16* Al, const bf16* Bh, const bf16* Bl,
                         const float* bias, void* C, int M, int N, int K, int act, int hl_out) {
    static int attr_done = 0;
    if (!attr_done) {
        cudaFuncSetAttribute(bgemm_kernel,
                             cudaFuncAttributeMaxDynamicSharedMemorySize, GEMM_SMEM);
        attr_done = 1;
    }
    dim3 g(N / 128, (M + 127) / 128);
    bgemm_kernel<<<g, 256, GEMM_SMEM>>>(Ah, Al, Bh, Bl, bias, C, M, N, K, act, hl_out);
}

// ------------------------- split / transpose preprocessing -------------------------
// elementwise fp32 -> bf16 hi/lo
__global__ void asplit_kernel(const float* __restrict__ src, bf16* __restrict__ dh,
                              bf16* __restrict__ dl, int n) {
    int i = blockIdx.x * blockDim.x + threadIdx.x;
    if (i >= n) return;
    bf16 h, l;
    bsplit(src[i], h, l);
    dh[i] = h; dl[i] = l;
}
// cell_x [NC,735] -> padded [NC,736] hi/lo
__global__ void pad_split_cellx(const float* __restrict__ src, bf16* __restrict__ dh,
                                bf16* __restrict__ dl) {
    int i = blockIdx.x * blockDim.x + threadIdx.x;
    if (i >= NC * FCP) return;
    int r = i / FCP, k = i - r * FCP;
    float v = (k < FC) ? src[(size_t)r * FC + k] : 0.f;
    bf16 h, l;
    bsplit(v, h, l);
    dh[i] = h; dl[i] = l;
}
// weight [Ksrc,N] fp32 -> transposed [N,K] hi/lo (K padded, zero fill)
__global__ void wsplit_kernel(const float* __restrict__ src, bf16* __restrict__ dh,
                              bf16* __restrict__ dl, int K, int N, int Ksrc) {
    __shared__ float tile[32][33];
    int kb = blockIdx.y * 32, nb = blockIdx.x * 32;
    int tx = threadIdx.x, ty = threadIdx.y;  // 32 x 8
    for (int i = ty; i < 32; i += 8) {
        int k = kb + i, n = nb + tx;
        tile[i][tx] = (k < Ksrc && n < N) ? src[(size_t)k * N + n] : 0.f;
    }
    __syncthreads();
    for (int i = ty; i < 32; i += 8) {
        int n = nb + i, k = kb + tx;
        if (n < N && k < K) {
            bf16 h, l;
            bsplit(tile[tx][i], h, l);
            dh[(size_t)n * K + k] = h;
            dl[(size_t)n * K + k] = l;
        }
    }
}

// ------------------------- CSR build -------------------------
__global__ void hist_kernel(const int* __restrict__ ei, int E, int n, int* __restrict__ cnt) {
    int i = blockIdx.x * blockDim.x + threadIdx.x;
    if (i >= E + n) return;
    int d = (i < E) ? ei[E + i] : (i - E);
    atomicAdd(&cnt[d], 1);
}

__global__ void scan_block_kernel(const int* __restrict__ cnt, int* __restrict__ off,
                                  int* __restrict__ bsum, int n) {
    __shared__ int sh[1024];
    int t = threadIdx.x;
    int i = blockIdx.x * 1024 + t;
    int v = (i < n) ? cnt[i] : 0;
    sh[t] = v;
    __syncthreads();
    for (int o = 1; o < 1024; o <<= 1) {
        int x = (t >= o) ? sh[t - o] : 0;
        __syncthreads();
        sh[t] += x;
        __syncthreads();
    }
    if (i < n) off[i] = sh[t] - v;
    if (t == 1023) bsum[blockIdx.x] = sh[t];
}

__global__ void scan_add_kernel(int* __restrict__ off, const int* __restrict__ bsum,
                                int nblocks, int n, int total) {
    __shared__ int pre[64];
    if (threadIdx.x == 0) {
        int s = 0;
        for (int b = 0; b < nblocks; b++) { pre[b] = s; s += bsum[b]; }
    }
    __syncthreads();
    int i = blockIdx.x * blockDim.x + threadIdx.x;
    if (i < n) off[i] += pre[i >> 10];
    if (i == 0) off[n] = total;
}

__global__ void scatter_kernel(const int* __restrict__ ei, int E, int n,
                               const int* __restrict__ off, int* __restrict__ fill,
                               int* __restrict__ csrc) {
    int i = blockIdx.x * blockDim.x + threadIdx.x;
    if (i >= E + n) return;
    int s, d;
    if (i < E) { s = ei[i]; d = ei[E + i]; } else { s = d = i - E; }
    int pos = off[d] + atomicAdd(&fill[d], 1);
    csrc[pos] = s;
}

// ------------------------- GAT pieces -------------------------
__global__ void node_dots_kernel(const float* __restrict__ x,
                                 const float* __restrict__ asrc,
                                 const float* __restrict__ adst,
                                 float* __restrict__ out_s, float* __restrict__ out_d,
                                 int n, int F) {
    int w = (int)((blockIdx.x * (size_t)blockDim.x + threadIdx.x) >> 5);
    int lane = threadIdx.x & 31;
    if (w >= n) return;
    const float* xr = x + (size_t)w * F;
    float s = 0.f, d = 0.f;
    for (int f = lane; f < F; f += 32) {
        float v = xr[f];
        s = fmaf(v, asrc[f], s);
        d = fmaf(v, adst[f], d);
    }
#pragma unroll
    for (int o = 16; o; o >>= 1) {
        s += __shfl_xor_sync(0xffffffffu, s, o);
        d += __shfl_xor_sync(0xffffffffu, d, o);
    }
    if (lane == 0) { out_s[w] = s; out_d[w] = d; }
}

__global__ void csr_softmax_kernel(const int* __restrict__ off, const int* __restrict__ csrc,
                                   const float* __restrict__ as_, const float* __restrict__ ad_,
                                   float* __restrict__ alpha, int n) {
    int w = (int)((blockIdx.x * (size_t)blockDim.x + threadIdx.x) >> 5);
    int lane = threadIdx.x & 31;
    if (w >= n) return;
    int beg = off[w], end = off[w + 1];
    float add = ad_[w];
    float m = -1e30f;
    for (int j = beg + lane; j < end; j += 32) {
        float e = as_[csrc[j]] + add;
        e = e > 0.f ? e : 0.2f * e;
        m = fmaxf(m, e);
    }
#pragma unroll
    for (int o = 16; o; o >>= 1) m = fmaxf(m, __shfl_xor_sync(0xffffffffu, m, o));
    float s = 0.f;
    for (int j = beg + lane; j < end; j += 32) {
        float e = as_[csrc[j]] + add;
        e = e > 0.f ? e : 0.2f * e;
        float v = expf(e - m);
        alpha[j] = v;
        s += v;
    }
#pragma unroll
    for (int o = 16; o; o >>= 1) s += __shfl_xor_sync(0xffffffffu, s, o);
    float inv = 1.f / s;
    for (int j = beg + lane; j < end; j += 32) alpha[j] *= inv;
}

// block-per-node gather; HL=0: fp32 out [n,F]; HL=1: bf16 hi [n,F] + bf16 lo [n,F]
template<int F, int HL>
__global__ void csr_gather_kernel(const int* __restrict__ off, const int* __restrict__ csrc,
                                  const float* __restrict__ alpha,
                                  const float* __restrict__ x,
                                  const float* __restrict__ bias,
                                  void* __restrict__ outp, int nnodes) {
    constexpr int FPT = F / 256;
    int d = blockIdx.x;
    int t = threadIdx.x;
    int beg = off[d], end = off[d + 1];
    float acc[FPT];
#pragma unroll
    for (int q = 0; q < FPT; q++) acc[q] = 0.f;

    int j = beg;
    for (; j + 1 < end; j += 2) {
        int s0 = csrc[j], s1 = csrc[j + 1];
        float a0 = alpha[j], a1 = alpha[j + 1];
        const float* x0 = x + (size_t)s0 * F;
        const float* x1 = x + (size_t)s1 * F;
#pragma unroll
        for (int q = 0; q < FPT; q++)
            acc[q] = fmaf(a1, x1[t + q * 256], fmaf(a0, x0[t + q * 256], acc[q]));
    }
    if (j < end) {
        int s0 = csrc[j];
        float a0 = alpha[j];
        const float* x0 = x + (size_t)s0 * F;
#pragma unroll
        for (int q = 0; q < FPT; q++)
            acc[q] = fmaf(a0, x0[t + q * 256], acc[q]);
    }
#pragma unroll
    for (int q = 0; q < FPT; q++) {
        float v = acc[q] + bias[t + q * 256];
        v = v > 0.f ? v : 0.f;
        if (!HL) {
            ((float*)outp)[(size_t)d * F + t + q * 256] = v;
        } else {
            bf16* oh = (bf16*)outp;
            bf16* ol = oh + (size_t)nnodes * F;
            bf16 h, l;
            bsplit(v, h, l);
            oh[(size_t)d * F + t + q * 256] = h;
            ol[(size_t)d * F + t + q * 256] = l;
        }
    }
}

// ------------------------- misc -------------------------
// comb row = [dagg[di], cagg2[ci]] split to bf16 hi/lo
__global__ void gather_comb_kernel(const float* __restrict__ dsrc, const float* __restrict__ csrc,
                                   const int* __restrict__ di, const int* __restrict__ ci,
                                   bf16* __restrict__ ch, bf16* __restrict__ cl) {
    int b = blockIdx.x;
    int t = threadIdx.x;  // 256
    float v0 = dsrc[(size_t)di[b] * 256 + t];
    float v1 = csrc[(size_t)ci[b] * 256 + t];
    bf16 h, l;
    bsplit(v0, h, l);
    ch[(size_t)b * 512 + t] = h;
    cl[(size_t)b * 512 + t] = l;
    bsplit(v1, h, l);
    ch[(size_t)b * 512 + 256 + t] = h;
    cl[(size_t)b * 512 + 256 + t] = l;
}

__global__ void head_final_kernel(const float* __restrict__ h, const float* __restrict__ W,
                                  const float* __restrict__ b, float* __restrict__ out) {
    size_t gt = blockIdx.x * (size_t)blockDim.x + threadIdx.x;
    int r = (int)(gt >> 5);
    int lane = threadIdx.x & 31;
    if (r >= BATCH) return;
    const float* hr = h + (size_t)r * 512;
    float s = 0.f;
    for (int f = lane; f < 512; f += 32) s = fmaf(hr[f], W[f], s);
#pragma unroll
    for (int o = 16; o; o >>= 1) s += __shfl_xor_sync(0xffffffffu, s, o);
    if (lane == 0) out[r] = s + b[0];
}

// ------------------------- host side -------------------------
static void build_csr(const int* ei, int E, int n, int* cnt, int* off, int* bsum, int* csrc) {
    cudaMemsetAsync(cnt, 0, n * sizeof(int));
    int total = E + n;
    hist_kernel<<<(total + 255) / 256, 256>>>(ei, E, n, cnt);
    int nblocks = (n + 1023) / 1024;
    scan_block_kernel<<<nblocks, 1024>>>(cnt, off, bsum, n);
    scan_add_kernel<<<(n + 255) / 256, 256>>>(off, bsum, nblocks, n, total);
    cudaMemsetAsync(cnt, 0, n * sizeof(int));
    scatter_kernel<<<(total + 255) / 256, 256>>>(ei, E, n, off, cnt, csrc);
}

template<typename T>
static T* sym(T* symbol) {
    void* p = nullptr;
    cudaGetSymbolAddress(&p, (const void*)symbol);
    return (T*)p;
}

extern "C" void kernel_launch(void* const* d_in, const int* in_sizes, int n_in,
                              void* d_out, int out_size) {
    const float* drug_x = (const float*)d_in[0];
    const float* cell_x = (const float*)d_in[1];
    const int* dei = (const int*)d_in[2];
    const int* cei = (const int*)d_in[3];
    const int* didx = (const int*)d_in[4];
    const int* cidx = (const int*)d_in[5];
    const float* dW1 = (const float*)d_in[6];  const float* db1 = (const float*)d_in[7];
    const float* cW1 = (const float*)d_in[8];  const float* cb1 = (const float*)d_in[9];
    const float* cW2 = (const float*)d_in[10]; const float* cb2 = (const float*)d_in[11];
    const float* gdW = (const float*)d_in[12]; const float* gdas = (const float*)d_in[13];
    const float* gdad = (const float*)d_in[14]; const float* gdb = (const float*)d_in[15];
    const float* g1W = (const float*)d_in[16]; const float* g1as = (const float*)d_in[17];
    const float* g1ad = (const float*)d_in[18]; const float* g1b = (const float*)d_in[19];
    const float* g2W = (const float*)d_in[20]; const float* g2as = (const float*)d_in[21];
    const float* g2ad = (const float*)d_in[22]; const float* g2b = (const float*)d_in[23];
    const float* rW1 = (const float*)d_in[24]; const float* rb1 = (const float*)d_in[25];
    const float* rW2 = (const float*)d_in[26]; const float* rb2 = (const float*)d_in[27];
    const float* rW3 = (const float*)d_in[28]; const float* rb3 = (const float*)d_in[29];
    float* out = (float*)d_out;

    // resolve device-global addresses
    float* p_dx = sym(g_dx);       float* p_dagg = sym(g_dagg);
    float* p_cx1 = sym(g_cx1);     float* p_cx2 = sym(g_cx2);
    float* p_cagg2 = sym(g_cagg2); float* p_h2 = sym(g_h2);
    float* p_as = sym(g_as);       float* p_ad = sym(g_ad);
    float* p_alpha = sym(g_alpha);
    int* p_off = sym(g_off); int* p_cnt = sym(g_cnt);
    int* p_bsum = sym(g_bsum); int* p_csrc = sym(g_csrc);
    bf16 *p_axh = sym(g_axh), *p_axl = sym(g_axl);
    bf16 *p_cxh = sym(g_cxh), *p_cxl = sym(g_cxl);
    bf16 *p_d0h = sym(g_d0h), *p_d0l = sym(g_d0l);
    bf16 *p_c0h = sym(g_c0h), *p_c0l = sym(g_c0l);
    bf16 *p_c1h = sym(g_c1h), *p_c1l = sym(g_c1l);
    bf16 *p_ca1h = sym(g_ca1h), *p_ca1l = sym(g_ca1l);
    bf16 *p_cmh = sym(g_cmh), *p_cml = sym(g_cml);
    bf16 *p_h1h = sym(g_h1h), *p_h1l = sym(g_h1l);
    bf16 *p_wd1h = sym(g_wd1h), *p_wd1l = sym(g_wd1l);
    bf16 *p_w1h = sym(g_w1h), *p_w1l = sym(g_w1l);
    bf16 *p_w2h = sym(g_w2h), *p_w2l = sym(g_w2l);
    bf16 *p_wgdh = sym(g_wgdh), *p_wgdl = sym(g_wgdl);
    bf16 *p_wg1h = sym(g_wg1h), *p_wg1l = sym(g_wg1l);
    bf16 *p_wg2h = sym(g_wg2h), *p_wg2l = sym(g_wg2l);
    bf16 *p_wr1h = sym(g_wr1h), *p_wr1l = sym(g_wr1l);
    bf16 *p_wr2h = sym(g_wr2h), *p_wr2l = sym(g_wr2l);

    dim3 wblk(32, 8);
    // ---- preprocessing: split inputs, transpose+split weights ----
    asplit_kernel<<<(ND * FD + 255) / 256, 256>>>(drug_x, p_axh, p_axl, ND * FD);
    pad_split_cellx<<<(NC * FCP + 255) / 256, 256>>>(cell_x, p_cxh, p_cxl);
    wsplit_kernel<<<dim3(256 / 32, 128 / 32), wblk>>>(dW1, p_wd1h, p_wd1l, 128, 256, 128);
    wsplit_kernel<<<dim3(1024 / 32, FCP / 32), wblk>>>(cW1, p_w1h, p_w1l, FCP, 1024, FC);
    wsplit_kernel<<<dim3(256 / 32, 1024 / 32), wblk>>>(cW2, p_w2h, p_w2l, 1024, 256, 1024);
    wsplit_kernel<<<dim3(256 / 32, 256 / 32), wblk>>>(gdW, p_wgdh, p_wgdl, 256, 256, 256);
    wsplit_kernel<<<dim3(1024 / 32, 256 / 32), wblk>>>(g1W, p_wg1h, p_wg1l, 256, 1024, 256);
    wsplit_kernel<<<dim3(256 / 32, 1024 / 32), wblk>>>(g2W, p_wg2h, p_wg2l, 1024, 256, 1024);
    wsplit_kernel<<<dim3(512 / 32, 512 / 32), wblk>>>(rW1, p_wr1h, p_wr1l, 512, 512, 512);
    wsplit_kernel<<<dim3(512 / 32, 512 / 32), wblk>>>(rW2, p_wr2h, p_wr2l, 512, 512, 512);

    // ---- feature transforms ----
    bgemm(p_axh, p_axl, p_wd1h, p_wd1l, db1, p_d0h, ND, 256, 128, 1, 1);    // d0 (hl)
    bgemm(p_cxh, p_cxl, p_w1h, p_w1l, cb1, p_c0h, NC, 1024, FCP, 1, 1);     // c0 (hl)
    bgemm(p_c0h, p_c0l, p_w2h, p_w2l, cb2, p_c1h, NC, 256, 1024, 1, 1);     // c1 (hl)

    // ---- drug GAT (256 -> 256) ----
    bgemm(p_d0h, p_d0l, p_wgdh, p_wgdl, nullptr, p_dx, ND, 256, 256, 0, 0); // dx fp32
    build_csr(dei, ED, ND, p_cnt, p_off, p_bsum, p_csrc);
    {
        size_t th = (size_t)ND * 32;
        node_dots_kernel<<<(unsigned)((th + 255) / 256), 256>>>(p_dx, gdas, gdad, p_as, p_ad, ND, 256);
        csr_softmax_kernel<<<(unsigned)((th + 255) / 256), 256>>>(p_off, p_csrc, p_as, p_ad, p_alpha, ND);
        csr_gather_kernel<256, 0><<<ND, 256>>>(p_off, p_csrc, p_alpha, p_dx, gdb, p_dagg, ND);
    }

    // ---- cell GAT1 (256 -> 1024) ----
    bgemm(p_c1h, p_c1l, p_wg1h, p_wg1l, nullptr, p_cx1, NC, 1024, 256, 0, 0);
    build_csr(cei, EC, NC, p_cnt, p_off, p_bsum, p_csrc);   // shared by GAT1 + GAT2
    {
        size_t th = (size_t)NC * 32;
        node_dots_kernel<<<(unsigned)((th + 255) / 256), 256>>>(p_cx1, g1as, g1ad, p_as, p_ad, NC, 1024);
        csr_softmax_kernel<<<(unsigned)((th + 255) / 256), 256>>>(p_off, p_csrc, p_as, p_ad, p_alpha, NC);
        csr_gather_kernel<1024, 1><<<NC, 256>>>(p_off, p_csrc, p_alpha, p_cx1, g1b, p_ca1h, NC);
    }

    // ---- cell GAT2 (1024 -> 256) ----
    bgemm(p_ca1h, p_ca1l, p_wg2h, p_wg2l, nullptr, p_cx2, NC, 256, 1024, 0, 0);
    {
        size_t th = (size_t)NC * 32;
        node_dots_kernel<<<(unsigned)((th + 255) / 256), 256>>>(p_cx2, g2as, g2ad, p_as, p_ad, NC, 256);
        csr_softmax_kernel<<<(unsigned)((th + 255) / 256), 256>>>(p_off, p_csrc, p_as, p_ad, p_alpha, NC);
        csr_gather_kernel<256, 0><<<NC, 256>>>(p_off, p_csrc, p_alpha, p_cx2, g2b, p_cagg2, NC);
    }

    // ---- pair gather + regression head ----
    gather_comb_kernel<<<BATCH, 256>>>(p_dagg, p_cagg2, didx, cidx, p_cmh, p_cml);
    bgemm(p_cmh, p_cml, p_wr1h, p_wr1l, rb1, p_h1h, BATCH, 512, 512, 2, 1);  // h1 (hl)
    bgemm(p_h1h, p_h1l, p_wr2h, p_wr2l, rb2, p_h2, BATCH, 512, 512, 2, 0);   // h2 fp32
    head_final_kernel<<<(BATCH * 32 + 255) / 256, 256>>>(p_h2, rW3, rb3, out);
}

// round 14
// speedup vs baseline: 2.7222x; 1.2232x over previous
#include <cuda_runtime.h>
#include <cuda_bf16.h>
#include <math.h>
#include <stdint.h>

// Problem dims (fixed by setup_inputs)
#define ND 50000
#define FD 128
#define NC 10000
#define FC 735
#define FCP 736        // padded K for cell MLP1
#define ED 800000
#define EC 160000
#define BATCH 16384

typedef __nv_bfloat16 bf16;
typedef __nv_bfloat162 bf162;

// ------------------------- scratch (device globals) -------------------------
__device__ float g_dx[ND * 256];
__device__ float g_dagg[ND * 256];
__device__ float g_cx1[NC * 1024];
__device__ float g_cx2[NC * 256];
__device__ float g_cagg2[NC * 256];
__device__ float g_h2[BATCH * 512];
__device__ float g_as[ND];
__device__ float g_ad[ND];
__device__ float g_alpha[ED + ND];
__device__ int   g_off[ND + 1];
__device__ int   g_cnt[ND];
__device__ int   g_bsum[64];
__device__ int   g_csrc[ED + ND];
// bf16 hi/lo activation tensors (GEMM inputs)
__device__ bf16 g_axh[ND * FD],    g_axl[ND * FD];
__device__ bf16 g_cxh[NC * FCP],   g_cxl[NC * FCP];
__device__ bf16 g_d0h[ND * 256],   g_d0l[ND * 256];
__device__ bf16 g_c0h[NC * 1024],  g_c0l[NC * 1024];
__device__ bf16 g_c1h[NC * 256],   g_c1l[NC * 256];
__device__ bf16 g_ca1h[NC * 1024], g_ca1l[NC * 1024];
__device__ bf16 g_cmh[BATCH * 512], g_cml[BATCH * 512];
__device__ bf16 g_h1h[BATCH * 512], g_h1l[BATCH * 512];
// bf16 hi/lo transposed weights [N,K]
__device__ bf16 g_wd1h[256 * 128],  g_wd1l[256 * 128];
__device__ bf16 g_w1h[1024 * FCP],  g_w1l[1024 * FCP];
__device__ bf16 g_w2h[256 * 1024],  g_w2l[256 * 1024];
__device__ bf16 g_wgdh[256 * 256],  g_wgdl[256 * 256];
__device__ bf16 g_wg1h[1024 * 256], g_wg1l[1024 * 256];
__device__ bf16 g_wg2h[256 * 1024], g_wg2l[256 * 1024];
__device__ bf16 g_wr1h[512 * 512],  g_wr1l[512 * 512];
__device__ bf16 g_wr2h[512 * 512],  g_wr2l[512 * 512];

// ------------------------- helpers -------------------------
#define SW128(x) ((x) ^ (((x) >> 3) & 0x70))

__device__ __forceinline__ void bsplit(float v, bf16& h, bf16& l) {
    h = __float2bfloat16_rn(v);
    l = __float2bfloat16_rn(v - __bfloat162float(h));
}
__device__ __forceinline__ void mma_bf16(float* c, const uint32_t* a, const uint32_t* b) {
    asm volatile("mma.sync.aligned.m16n8k16.row.col.f32.bf16.bf16.f32 "
                 "{%0,%1,%2,%3},{%4,%5,%6,%7},{%8,%9},{%0,%1,%2,%3};"
                 : "+f"(c[0]), "+f"(c[1]), "+f"(c[2]), "+f"(c[3])
                 : "r"(a[0]), "r"(a[1]), "r"(a[2]), "r"(a[3]),
                   "r"(b[0]), "r"(b[1]));
}
__device__ __forceinline__ void ldm_x4(uint32_t* r, uint32_t addr) {
    asm volatile("ldmatrix.sync.aligned.m8n8.x4.shared.b16 {%0,%1,%2,%3}, [%4];"
                 : "=r"(r[0]), "=r"(r[1]), "=r"(r[2]), "=r"(r[3]) : "r"(addr));
}
__device__ __forceinline__ void cp16(uint32_t dst, const void* src, int sz) {
    asm volatile("cp.async.cg.shared.global [%0], [%1], 16, %2;"
                 :: "r"(dst), "l"(src), "r"(sz) : "memory");
}

// ------------------------- bf16x2 tensor-core GEMM -------------------------
// C[M,N] = act(A@B + bias); A hi/lo bf16 [M,K]; B hi/lo bf16 [N,K] pre-transposed.
// K%32==0, N%128==0. acc = Ah*Bh + Al*Bh + Ah*Bl (fp32 accum).
#define STAGE 32768
#define NPIPE 3
#define GEMM_SMEM (NPIPE * STAGE)

__global__ void __launch_bounds__(256, 2)
bgemm_kernel(const bf16* __restrict__ Ah, const bf16* __restrict__ Al,
             const bf16* __restrict__ Bh, const bf16* __restrict__ Bl,
             const float* __restrict__ bias, void* __restrict__ Cp,
             int M, int N, int K, int act, int hl_out) {
    extern __shared__ char smem[];
    const int tid = threadIdx.x;
    const int wid = tid >> 5, lane = tid & 31;
    const int gq = lane >> 2, tg = lane & 3;
    const int warp_m = wid & 3, warp_n = wid >> 2;   // 4x2 warp grid, tile 32x64
    const int mbase = blockIdx.y * 128, nbase = blockIdx.x * 128;
    const uint32_t sB = (uint32_t)__cvta_generic_to_shared(smem);

    const int nk = K >> 5;

    // stage layout: A [128 rows][128B: hi k0..31 | lo k0..31], B same (n rows)
    auto load_stage = [&](int ci) {
        const uint32_t sb = sB + (ci % NPIPE) * STAGE;
        const int k0 = ci << 5;
#pragma unroll
        for (int p = 0; p < 4; p++) {
            int uid = tid + p * 256;
            int row = uid >> 3, u = uid & 7;
            int gm = mbase + row;
            const bf16* src = (u < 4 ? Ah : Al) + (size_t)(gm < M ? gm : 0) * K + k0 + (u & 3) * 8;
            cp16(sb + SW128((uint32_t)(row * 128 + u * 16)), src, (gm < M) ? 16 : 0);
        }
#pragma unroll
        for (int p = 0; p < 4; p++) {
            int uid = tid + p * 256;
            int row = uid >> 3, u = uid & 7;
            const bf16* src = (u < 4 ? Bh : Bl) + (size_t)(nbase + row) * K + k0 + (u & 3) * 8;
            cp16(sb + 16384 + SW128((uint32_t)(row * 128 + u * 16)), src, 16);
        }
    };

    load_stage(0);
    asm volatile("cp.async.commit_group;" ::: "memory");
    load_stage(1);
    asm volatile("cp.async.commit_group;" ::: "memory");

    float c[2][8][4];
#pragma unroll
    for (int mt = 0; mt < 2; mt++)
#pragma unroll
        for (int nt = 0; nt < 8; nt++)
#pragma unroll
            for (int j = 0; j < 4; j++) c[mt][nt][j] = 0.f;

    // ldmatrix lane-invariant address components
    const int lm8 = (lane >> 3) & 1;     // m&1
    const int l16 = (lane >> 4) & 1;     // m>>1
    const int lrw = lane & 7;
    // A: matrix m -> row += (m&1)*8, colbyte += (m>>1)*16
    const int arow = warp_m * 32 + lm8 * 8 + lrw;          // + mt*16
    const int acx = l16 * 16;                              // + h*64 + s*32
    // B: matrix m -> n += (m>>1)*8, colbyte += (m&1)*16
    const int brow = warp_n * 64 + l16 * 8 + lrw;          // + j*16
    const int bcx = lm8 * 16;                              // + h*64 + s*32

    for (int t = 0; t < nk; t++) {
        if (t + 2 < nk) load_stage(t + 2);
        asm volatile("cp.async.commit_group;" ::: "memory");
        asm volatile("cp.async.wait_group 2;" ::: "memory");
        __syncthreads();

        const uint32_t aBase = sB + (t % NPIPE) * STAGE;
        const uint32_t bBase = aBase + 16384;

#pragma unroll
        for (int s = 0; s < 2; s++) {
            uint32_t af[2][2][4];
#pragma unroll
            for (int mt = 0; mt < 2; mt++)
#pragma unroll
                for (int h = 0; h < 2; h++) {
                    int row = arow + mt * 16;
                    int col = (h * 64 + s * 32 + acx) ^ ((row & 7) << 4);
                    ldm_x4(af[mt][h], aBase + (uint32_t)(row * 128 + col));
                }
#pragma unroll
            for (int j = 0; j < 4; j++) {
                uint32_t bh[4], bl[4];
                {
                    int n = brow + j * 16;
                    uint32_t base = bBase + (uint32_t)(n * 128);
                    int x0 = (s * 32 + bcx) ^ ((n & 7) << 4);
                    int x1 = (64 + s * 32 + bcx) ^ ((n & 7) << 4);
                    ldm_x4(bh, base + (uint32_t)x0);
                    ldm_x4(bl, base + (uint32_t)x1);
                }
#pragma unroll
                for (int p = 0; p < 2; p++) {
                    int nt = 2 * j + p;
#pragma unroll
                    for (int mt = 0; mt < 2; mt++) {
                        float* cc = c[mt][nt];
                        mma_bf16(cc, af[mt][0], &bh[p * 2]);   // hi*hi
                        mma_bf16(cc, af[mt][1], &bh[p * 2]);   // lo*hi
                        mma_bf16(cc, af[mt][0], &bl[p * 2]);   // hi*lo
                    }
                }
            }
        }
        __syncthreads();
    }

    // ---- epilogue ----
#pragma unroll
    for (int mt = 0; mt < 2; mt++) {
        int row0 = mbase + warp_m * 32 + mt * 16 + gq;
#pragma unroll
        for (int nt = 0; nt < 8; nt++) {
            int col = nbase + warp_n * 64 + nt * 8 + 2 * tg;
            float b0 = bias ? bias[col] : 0.f;
            float b1 = bias ? bias[col + 1] : 0.f;
#pragma unroll
            for (int h = 0; h < 2; h++) {
                int row = row0 + h * 8;
                if (row >= M) continue;
                float v0 = c[mt][nt][h * 2 + 0] + b0;
                float v1 = c[mt][nt][h * 2 + 1] + b1;
                if (act == 1) {
                    v0 = v0 > 0.f ? v0 : 0.f;
                    v1 = v1 > 0.f ? v1 : 0.f;
                } else if (act == 2) {
                    v0 = v0 > 0.f ? v0 : (expf(v0) - 1.f);
                    v1 = v1 > 0.f ? v1 : (expf(v1) - 1.f);
                }
                if (!hl_out) {
                    *(float2*)((float*)Cp + (size_t)row * N + col) = make_float2(v0, v1);
                } else {
                    bf16* Ch = (bf16*)Cp;
                    bf16* Cl = Ch + (size_t)M * N;
                    bf16 h0, l0, h1, l1;
                    bsplit(v0, h0, l0);
                    bsplit(v1, h1, l1);
                    bf162 hv; hv.x = h0; hv.y = h1;
                    bf162 lv; lv.x = l0; lv.y = l1;
                    *(bf162*)&Ch[(size_t)row * N + col] = hv;
                    *(bf162*)&Cl[(size_t)row * N + col] = lv;
                }
            }
        }
    }
}

static inline void bgemm(const bf16* Ah, const bf16* Al, const bf16* Bh, const bf16* Bl,
                         const float* bias, void* C, int M, int N, int K, int act, int hl_out) {
    static int attr_done = 0;
    if (!attr_done) {
        cudaFuncSetAttribute(bgemm_kernel,
                             cudaFuncAttributeMaxDynamicSharedMemorySize, GEMM_SMEM);
        attr_done = 1;
    }
    dim3 g(N / 128, (M + 127) / 128);
    bgemm_kernel<<<g, 256, GEMM_SMEM>>>(Ah, Al, Bh, Bl, bias, C, M, N, K, act, hl_out);
}

// ------------------------- split / transpose preprocessing -------------------------
__global__ void asplit_kernel(const float* __restrict__ src, bf16* __restrict__ dh,
                              bf16* __restrict__ dl, int n) {
    int i = blockIdx.x * blockDim.x + threadIdx.x;
    if (i >= n) return;
    bf16 h, l;
    bsplit(src[i], h, l);
    dh[i] = h; dl[i] = l;
}
__global__ void pad_split_cellx(const float* __restrict__ src, bf16* __restrict__ dh,
                                bf16* __restrict__ dl) {
    int i = blockIdx.x * blockDim.x + threadIdx.x;
    if (i >= NC * FCP) return;
    int r = i / FCP, k = i - r * FCP;
    float v = (k < FC) ? src[(size_t)r * FC + k] : 0.f;
    bf16 h, l;
    bsplit(v, h, l);
    dh[i] = h; dl[i] = l;
}
__global__ void wsplit_kernel(const float* __restrict__ src, bf16* __restrict__ dh,
                              bf16* __restrict__ dl, int K, int N, int Ksrc) {
    __shared__ float tile[32][33];
    int kb = blockIdx.y * 32, nb = blockIdx.x * 32;
    int tx = threadIdx.x, ty = threadIdx.y;  // 32 x 8
    for (int i = ty; i < 32; i += 8) {
        int k = kb + i, n = nb + tx;
        tile[i][tx] = (k < Ksrc && n < N) ? src[(size_t)k * N + n] : 0.f;
    }
    __syncthreads();
    for (int i = ty; i < 32; i += 8) {
        int n = nb + i, k = kb + tx;
        if (n < N && k < K) {
            bf16 h, l;
            bsplit(tile[tx][i], h, l);
            dh[(size_t)n * K + k] = h;
            dl[(size_t)n * K + k] = l;
        }
    }
}

// ------------------------- CSR build -------------------------
__global__ void hist_kernel(const int* __restrict__ ei, int E, int n, int* __restrict__ cnt) {
    int i = blockIdx.x * blockDim.x + threadIdx.x;
    if (i >= E + n) return;
    int d = (i < E) ? ei[E + i] : (i - E);
    atomicAdd(&cnt[d], 1);
}

__global__ void scan_block_kernel(const int* __restrict__ cnt, int* __restrict__ off,
                                  int* __restrict__ bsum, int n) {
    __shared__ int sh[1024];
    int t = threadIdx.x;
    int i = blockIdx.x * 1024 + t;
    int v = (i < n) ? cnt[i] : 0;
    sh[t] = v;
    __syncthreads();
    for (int o = 1; o < 1024; o <<= 1) {
        int x = (t >= o) ? sh[t - o] : 0;
        __syncthreads();
        sh[t] += x;
        __syncthreads();
    }
    if (i < n) off[i] = sh[t] - v;
    if (t == 1023) bsum[blockIdx.x] = sh[t];
}

__global__ void scan_add_kernel(int* __restrict__ off, const int* __restrict__ bsum,
                                int nblocks, int n, int total) {
    __shared__ int pre[64];
    if (threadIdx.x == 0) {
        int s = 0;
        for (int b = 0; b < nblocks; b++) { pre[b] = s; s += bsum[b]; }
    }
    __syncthreads();
    int i = blockIdx.x * blockDim.x + threadIdx.x;
    if (i < n) off[i] += pre[i >> 10];
    if (i == 0) off[n] = total;
}

__global__ void scatter_kernel(const int* __restrict__ ei, int E, int n,
                               const int* __restrict__ off, int* __restrict__ fill,
                               int* __restrict__ csrc) {
    int i = blockIdx.x * blockDim.x + threadIdx.x;
    if (i >= E + n) return;
    int s, d;
    if (i < E) { s = ei[i]; d = ei[E + i]; } else { s = d = i - E; }
    int pos = off[d] + atomicAdd(&fill[d], 1);
    csrc[pos] = s;
}

// ------------------------- GAT pieces -------------------------
__global__ void node_dots_kernel(const float* __restrict__ x,
                                 const float* __restrict__ asrc,
                                 const float* __restrict__ adst,
                                 float* __restrict__ out_s, float* __restrict__ out_d,
                                 int n, int F) {
    int w = (int)((blockIdx.x * (size_t)blockDim.x + threadIdx.x) >> 5);
    int lane = threadIdx.x & 31;
    if (w >= n) return;
    const float4* xr = (const float4*)(x + (size_t)w * F);
    const float4* a4 = (const float4*)asrc;
    const float4* d4 = (const float4*)adst;
    float s = 0.f, d = 0.f;
    for (int f = lane; f < (F >> 2); f += 32) {
        float4 v = xr[f], a = a4[f], b = d4[f];
        s = fmaf(v.x, a.x, fmaf(v.y, a.y, fmaf(v.z, a.z, fmaf(v.w, a.w, s))));
        d = fmaf(v.x, b.x, fmaf(v.y, b.y, fmaf(v.z, b.z, fmaf(v.w, b.w, d))));
    }
#pragma unroll
    for (int o = 16; o; o >>= 1) {
        s += __shfl_xor_sync(0xffffffffu, s, o);
        d += __shfl_xor_sync(0xffffffffu, d, o);
    }
    if (lane == 0) { out_s[w] = s; out_d[w] = d; }
}

__global__ void csr_softmax_kernel(const int* __restrict__ off, const int* __restrict__ csrc,
                                   const float* __restrict__ as_, const float* __restrict__ ad_,
                                   float* __restrict__ alpha, int n) {
    int w = (int)((blockIdx.x * (size_t)blockDim.x + threadIdx.x) >> 5);
    int lane = threadIdx.x & 31;
    if (w >= n) return;
    int beg = off[w], end = off[w + 1];
    float add = ad_[w];
    float m = -1e30f;
    for (int j = beg + lane; j < end; j += 32) {
        float e = as_[csrc[j]] + add;
        e = e > 0.f ? e : 0.2f * e;
        m = fmaxf(m, e);
    }
#pragma unroll
    for (int o = 16; o; o >>= 1) m = fmaxf(m, __shfl_xor_sync(0xffffffffu, m, o));
    float s = 0.f;
    for (int j = beg + lane; j < end; j += 32) {
        float e = as_[csrc[j]] + add;
        e = e > 0.f ? e : 0.2f * e;
        float v = expf(e - m);
        alpha[j] = v;
        s += v;
    }
#pragma unroll
    for (int o = 16; o; o >>= 1) s += __shfl_xor_sync(0xffffffffu, s, o);
    float inv = 1.f / s;
    for (int j = beg + lane; j < end; j += 32) alpha[j] *= inv;
}

// Gather with float4 per thread. GPB node-groups per 256-thread block.
// HL=0: fp32 out [n,F]; HL=1: bf16 hi [n,F] + bf16 lo [n,F]
template<int F, int HL, int GPB>
__global__ void csr_gather_kernel(const int* __restrict__ off, const int* __restrict__ csrc,
                                  const float* __restrict__ alpha,
                                  const float* __restrict__ x,
                                  const float* __restrict__ bias,
                                  void* __restrict__ outp, int nnodes) {
    constexpr int TPG = 256 / GPB;     // == F/4
    int g = threadIdx.x / TPG;
    int u = threadIdx.x % TPG;
    int d = blockIdx.x * GPB + g;
    if (d >= nnodes) return;
    int beg = off[d], end = off[d + 1];
    const float4* x4 = (const float4*)x;
    float4 acc = make_float4(0.f, 0.f, 0.f, 0.f);
    int j = beg;
    for (; j + 1 < end; j += 2) {
        int s0 = csrc[j], s1 = csrc[j + 1];
        float a0 = alpha[j], a1 = alpha[j + 1];
        float4 v0 = x4[(size_t)s0 * (F / 4) + u];
        float4 v1 = x4[(size_t)s1 * (F / 4) + u];
        acc.x = fmaf(a1, v1.x, fmaf(a0, v0.x, acc.x));
        acc.y = fmaf(a1, v1.y, fmaf(a0, v0.y, acc.y));
        acc.z = fmaf(a1, v1.z, fmaf(a0, v0.z, acc.z));
        acc.w = fmaf(a1, v1.w, fmaf(a0, v0.w, acc.w));
    }
    if (j < end) {
        int s0 = csrc[j];
        float a0 = alpha[j];
        float4 v0 = x4[(size_t)s0 * (F / 4) + u];
        acc.x = fmaf(a0, v0.x, acc.x);
        acc.y = fmaf(a0, v0.y, acc.y);
        acc.z = fmaf(a0, v0.z, acc.z);
        acc.w = fmaf(a0, v0.w, acc.w);
    }
    float4 bv = ((const float4*)bias)[u];
    acc.x += bv.x; acc.y += bv.y; acc.z += bv.z; acc.w += bv.w;
    acc.x = acc.x > 0.f ? acc.x : 0.f;
    acc.y = acc.y > 0.f ? acc.y : 0.f;
    acc.z = acc.z > 0.f ? acc.z : 0.f;
    acc.w = acc.w > 0.f ? acc.w : 0.f;
    if (!HL) {
        ((float4*)outp)[(size_t)d * (F / 4) + u] = acc;
    } else {
        bf16* oh = (bf16*)outp;
        bf16* ol = oh + (size_t)nnodes * F;
        bf16 h0, l0, h1, l1, h2, l2, h3, l3;
        bsplit(acc.x, h0, l0); bsplit(acc.y, h1, l1);
        bsplit(acc.z, h2, l2); bsplit(acc.w, h3, l3);
        bf162 hv0; hv0.x = h0; hv0.y = h1;
        bf162 hv1; hv1.x = h2; hv1.y = h3;
        bf162 lv0; lv0.x = l0; lv0.y = l1;
        bf162 lv1; lv1.x = l2; lv1.y = l3;
        size_t base = (size_t)d * F + u * 4;
        *(bf162*)&oh[base] = hv0; *(bf162*)&oh[base + 2] = hv1;
        *(bf162*)&ol[base] = lv0; *(bf162*)&ol[base + 2] = lv1;
    }
}

// ------------------------- misc -------------------------
__global__ void gather_comb_kernel(const float* __restrict__ dsrc, const float* __restrict__ csrc,
                                   const int* __restrict__ di, const int* __restrict__ ci,
                                   bf16* __restrict__ ch, bf16* __restrict__ cl) {
    int b = blockIdx.x;
    int t = threadIdx.x;   // 128 threads; t<64: drug float4, t>=64: cell float4
    int half = t >> 6, u = t & 63;
    const float4* src = half ? (const float4*)(csrc + (size_t)ci[b] * 256)
                             : (const float4*)(dsrc + (size_t)di[b] * 256);
    float4 v = src[u];
    bf16 h0, l0, h1, l1, h2, l2, h3, l3;
    bsplit(v.x, h0, l0); bsplit(v.y, h1, l1);
    bsplit(v.z, h2, l2); bsplit(v.w, h3, l3);
    bf162 hv0; hv0.x = h0; hv0.y = h1;
    bf162 hv1; hv1.x = h2; hv1.y = h3;
    bf162 lv0; lv0.x = l0; lv0.y = l1;
    bf162 lv1; lv1.x = l2; lv1.y = l3;
    size_t base = (size_t)b * 512 + half * 256 + u * 4;
    *(bf162*)&ch[base] = hv0; *(bf162*)&ch[base + 2] = hv1;
    *(bf162*)&cl[base] = lv0; *(bf162*)&cl[base + 2] = lv1;
}

__global__ void head_final_kernel(const float* __restrict__ h, const float* __restrict__ W,
                                  const float* __restrict__ b, float* __restrict__ out) {
    size_t gt = blockIdx.x * (size_t)blockDim.x + threadIdx.x;
    int r = (int)(gt >> 5);
    int lane = threadIdx.x & 31;
    if (r >= BATCH) return;
    const float4* hr = (const float4*)(h + (size_t)r * 512);
    const float4* w4 = (const float4*)W;
    float s = 0.f;
#pragma unroll
    for (int i = 0; i < 4; i++) {
        int f = lane + i * 32;
        float4 v = hr[f], w = w4[f];
        s = fmaf(v.x, w.x, fmaf(v.y, w.y, fmaf(v.z, w.z, fmaf(v.w, w.w, s))));
    }
#pragma unroll
    for (int o = 16; o; o >>= 1) s += __shfl_xor_sync(0xffffffffu, s, o);
    if (lane == 0) out[r] = s + b[0];
}

// ------------------------- host side -------------------------
static void build_csr(const int* ei, int E, int n, int* cnt, int* off, int* bsum, int* csrc) {
    cudaMemsetAsync(cnt, 0, n * sizeof(int));
    int total = E + n;
    hist_kernel<<<(total + 255) / 256, 256>>>(ei, E, n, cnt);
    int nblocks = (n + 1023) / 1024;
    scan_block_kernel<<<nblocks, 1024>>>(cnt, off, bsum, n);
    scan_add_kernel<<<(n + 255) / 256, 256>>>(off, bsum, nblocks, n, total);
    cudaMemsetAsync(cnt, 0, n * sizeof(int));
    scatter_kernel<<<(total + 255) / 256, 256>>>(ei, E, n, off, cnt, csrc);
}

template<typename T>
static T* sym(T* symbol) {
    void* p = nullptr;
    cudaGetSymbolAddress(&p, (const void*)symbol);
    return (T*)p;
}

extern "C" void kernel_launch(void* const* d_in, const int* in_sizes, int n_in,
                              void* d_out, int out_size) {
    const float* drug_x = (const float*)d_in[0];
    const float* cell_x = (const float*)d_in[1];
    const int* dei = (const int*)d_in[2];
    const int* cei = (const int*)d_in[3];
    const int* didx = (const int*)d_in[4];
    const int* cidx = (const int*)d_in[5];
    const float* dW1 = (const float*)d_in[6];  const float* db1 = (const float*)d_in[7];
    const float* cW1 = (const float*)d_in[8];  const float* cb1 = (const float*)d_in[9];
    const float* cW2 = (const float*)d_in[10]; const float* cb2 = (const float*)d_in[11];
    const float* gdW = (const float*)d_in[12]; const float* gdas = (const float*)d_in[13];
    const float* gdad = (const float*)d_in[14]; const float* gdb = (const float*)d_in[15];
    const float* g1W = (const float*)d_in[16]; const float* g1as = (const float*)d_in[17];
    const float* g1ad = (const float*)d_in[18]; const float* g1b = (const float*)d_in[19];
    const float* g2W = (const float*)d_in[20]; const float* g2as = (const float*)d_in[21];
    const float* g2ad = (const float*)d_in[22]; const float* g2b = (const float*)d_in[23];
    const float* rW1 = (const float*)d_in[24]; const float* rb1 = (const float*)d_in[25];
    const float* rW2 = (const float*)d_in[26]; const float* rb2 = (const float*)d_in[27];
    const float* rW3 = (const float*)d_in[28]; const float* rb3 = (const float*)d_in[29];
    float* out = (float*)d_out;

    float* p_dx = sym(g_dx);       float* p_dagg = sym(g_dagg);
    float* p_cx1 = sym(g_cx1);     float* p_cx2 = sym(g_cx2);
    float* p_cagg2 = sym(g_cagg2); float* p_h2 = sym(g_h2);
    float* p_as = sym(g_as);       float* p_ad = sym(g_ad);
    float* p_alpha = sym(g_alpha);
    int* p_off = sym(g_off); int* p_cnt = sym(g_cnt);
    int* p_bsum = sym(g_bsum); int* p_csrc = sym(g_csrc);
    bf16 *p_axh = sym(g_axh), *p_axl = sym(g_axl);
    bf16 *p_cxh = sym(g_cxh), *p_cxl = sym(g_cxl);
    bf16 *p_d0h = sym(g_d0h), *p_d0l = sym(g_d0l);
    bf16 *p_c0h = sym(g_c0h), *p_c0l = sym(g_c0l);
    bf16 *p_c1h = sym(g_c1h), *p_c1l = sym(g_c1l);
    bf16 *p_ca1h = sym(g_ca1h), *p_ca1l = sym(g_ca1l);
    bf16 *p_cmh = sym(g_cmh), *p_cml = sym(g_cml);
    bf16 *p_h1h = sym(g_h1h), *p_h1l = sym(g_h1l);
    bf16 *p_wd1h = sym(g_wd1h), *p_wd1l = sym(g_wd1l);
    bf16 *p_w1h = sym(g_w1h), *p_w1l = sym(g_w1l);
    bf16 *p_w2h = sym(g_w2h), *p_w2l = sym(g_w2l);
    bf16 *p_wgdh = sym(g_wgdh), *p_wgdl = sym(g_wgdl);
    bf16 *p_wg1h = sym(g_wg1h), *p_wg1l = sym(g_wg1l);
    bf16 *p_wg2h = sym(g_wg2h), *p_wg2l = sym(g_wg2l);
    bf16 *p_wr1h = sym(g_wr1h), *p_wr1l = sym(g_wr1l);
    bf16 *p_wr2h = sym(g_wr2h), *p_wr2l = sym(g_wr2l);

    dim3 wblk(32, 8);
    // ---- preprocessing: split inputs, transpose+split weights ----
    asplit_kernel<<<(ND * FD + 255) / 256, 256>>>(drug_x, p_axh, p_axl, ND * FD);
    pad_split_cellx<<<(NC * FCP + 255) / 256, 256>>>(cell_x, p_cxh, p_cxl);
    wsplit_kernel<<<dim3(256 / 32, 128 / 32), wblk>>>(dW1, p_wd1h, p_wd1l, 128, 256, 128);
    wsplit_kernel<<<dim3(1024 / 32, FCP / 32), wblk>>>(cW1, p_w1h, p_w1l, FCP, 1024, FC);
    wsplit_kernel<<<dim3(256 / 32, 1024 / 32), wblk>>>(cW2, p_w2h, p_w2l, 1024, 256, 1024);
    wsplit_kernel<<<dim3(256 / 32, 256 / 32), wblk>>>(gdW, p_wgdh, p_wgdl, 256, 256, 256);
    wsplit_kernel<<<dim3(1024 / 32, 256 / 32), wblk>>>(g1W, p_wg1h, p_wg1l, 256, 1024, 256);
    wsplit_kernel<<<dim3(256 / 32, 1024 / 32), wblk>>>(g2W, p_wg2h, p_wg2l, 1024, 256, 1024);
    wsplit_kernel<<<dim3(512 / 32, 512 / 32), wblk>>>(rW1, p_wr1h, p_wr1l, 512, 512, 512);
    wsplit_kernel<<<dim3(512 / 32, 512 / 32), wblk>>>(rW2, p_wr2h, p_wr2l, 512, 512, 512);

    // ---- feature transforms ----
    bgemm(p_axh, p_axl, p_wd1h, p_wd1l, db1, p_d0h, ND, 256, 128, 1, 1);
    bgemm(p_cxh, p_cxl, p_w1h, p_w1l, cb1, p_c0h, NC, 1024, FCP, 1, 1);
    bgemm(p_c0h, p_c0l, p_w2h, p_w2l, cb2, p_c1h, NC, 256, 1024, 1, 1);

    // ---- drug GAT (256 -> 256) ----
    bgemm(p_d0h, p_d0l, p_wgdh, p_wgdl, nullptr, p_dx, ND, 256, 256, 0, 0);
    build_csr(dei, ED, ND, p_cnt, p_off, p_bsum, p_csrc);
    {
        size_t th = (size_t)ND * 32;
        node_dots_kernel<<<(unsigned)((th + 255) / 256), 256>>>(p_dx, gdas, gdad, p_as, p_ad, ND, 256);
        csr_softmax_kernel<<<(unsigned)((th + 255) / 256), 256>>>(p_off, p_csrc, p_as, p_ad, p_alpha, ND);
        csr_gather_kernel<256, 0, 4><<<(ND + 3) / 4, 256>>>(p_off, p_csrc, p_alpha, p_dx, gdb, p_dagg, ND);
    }

    // ---- cell GAT1 (256 -> 1024) ----
    bgemm(p_c1h, p_c1l, p_wg1h, p_wg1l, nullptr, p_cx1, NC, 1024, 256, 0, 0);
    build_csr(cei, EC, NC, p_cnt, p_off, p_bsum, p_csrc);   // shared by GAT1 + GAT2
    {
        size_t th = (size_t)NC * 32;
        node_dots_kernel<<<(unsigned)((th + 255) / 256), 256>>>(p_cx1, g1as, g1ad, p_as, p_ad, NC, 1024);
        csr_softmax_kernel<<<(unsigned)((th + 255) / 256), 256>>>(p_off, p_csrc, p_as, p_ad, p_alpha, NC);
        csr_gather_kernel<1024, 1, 1><<<NC, 256>>>(p_off, p_csrc, p_alpha, p_cx1, g1b, p_ca1h, NC);
    }

    // ---- cell GAT2 (1024 -> 256) ----
    bgemm(p_ca1h, p_ca1l, p_wg2h, p_wg2l, nullptr, p_cx2, NC, 256, 1024, 0, 0);
    {
        size_t th = (size_t)NC * 32;
        node_dots_kernel<<<(unsigned)((th + 255) / 256), 256>>>(p_cx2, g2as, g2ad, p_as, p_ad, NC, 256);
        csr_softmax_kernel<<<(unsigned)((th + 255) / 256), 256>>>(p_off, p_csrc, p_as, p_ad, p_alpha, NC);
        csr_gather_kernel<256, 0, 4><<<(NC + 3) / 4, 256>>>(p_off, p_csrc, p_alpha, p_cx2, g2b, p_cagg2, NC);
    }

    // ---- pair gather + regression head ----
    gather_comb_kernel<<<BATCH, 128>>>(p_dagg, p_cagg2, didx, cidx, p_cmh, p_cml);
    bgemm(p_cmh, p_cml, p_wr1h, p_wr1l, rb1, p_h1h, BATCH, 512, 512, 2, 1);
    bgemm(p_h1h, p_h1l, p_wr2h, p_wr2l, rb2, p_h2, BATCH, 512, 512, 2, 0);
    head_final_kernel<<<(BATCH * 32 + 255) / 256, 256>>>(p_h2, rW3, rb3, out);
}